// round 11
// baseline (speedup 1.0000x reference)
#include <cuda_runtime.h>
#include <cuda_fp16.h>
#include <math.h>
#include <stdint.h>

// ---------------------------------------------------------------------------
// Problem constants (B=1, S=4096, DIM=1536, HEADS=12, HEAD_DIM=128)
// ---------------------------------------------------------------------------
#define SEQ    4096
#define DIM    1536
#define NHEADS 12
#define HDIM   128
#define EPS    1e-6f

// Scratch (allocation-free rule: __device__ globals)
__device__ __half g_xh[SEQ * DIM];
__device__ __half g_qh[SEQ * DIM];
__device__ __half g_kh[SEQ * DIM];
__device__ __half g_vh[SEQ * DIM];
__device__ __half g_attnh[SEQ * DIM];
__device__ __half g_wqh[DIM * DIM];
__device__ __half g_wkh[DIM * DIM];
__device__ __half g_wvh[DIM * DIM];
__device__ __half g_woh[DIM * DIM];
__device__ __half g_vt[NHEADS * HDIM * SEQ];   // V transposed: [h][d][s]
__device__ float  g_trig[SEQ * 64 * 2];        // cos,sin per (pos, pair)

// ---------------------------------------------------------------------------
// Helpers
// ---------------------------------------------------------------------------
__device__ __forceinline__ unsigned ld32h(const __half* p) {
    return *(const unsigned*)p;
}

// D += A*B, m16n8k16, fp16 inputs, f32 accumulate
__device__ __forceinline__ void mma_f16(float* d, const unsigned* a,
                                        unsigned b0, unsigned b1) {
    asm volatile(
        "mma.sync.aligned.m16n8k16.row.col.f32.f16.f16.f32 "
        "{%0,%1,%2,%3}, {%4,%5,%6,%7}, {%8,%9}, {%0,%1,%2,%3};\n"
        : "+f"(d[0]), "+f"(d[1]), "+f"(d[2]), "+f"(d[3])
        : "r"(a[0]), "r"(a[1]), "r"(a[2]), "r"(a[3]), "r"(b0), "r"(b1));
}

// ---------------------------------------------------------------------------
// Prep: fp32 -> fp16, 5 segments in one launch (y: 0=x, 1..4=Wq,Wk,Wv,Wo)
// ---------------------------------------------------------------------------
__global__ __launch_bounds__(256) void to_half_all_kernel(
    const float* __restrict__ x,  const float* __restrict__ Wq,
    const float* __restrict__ Wk, const float* __restrict__ Wv,
    const float* __restrict__ Wo)
{
    const int seg = blockIdx.y;
    const float* src;
    __half* dst;
    int n4;
    if (seg == 0)      { src = x;  dst = g_xh;  n4 = SEQ * DIM / 4; }
    else if (seg == 1) { src = Wq; dst = g_wqh; n4 = DIM * DIM / 4; }
    else if (seg == 2) { src = Wk; dst = g_wkh; n4 = DIM * DIM / 4; }
    else if (seg == 3) { src = Wv; dst = g_wvh; n4 = DIM * DIM / 4; }
    else               { src = Wo; dst = g_woh; n4 = DIM * DIM / 4; }

    int i = blockIdx.x * blockDim.x + threadIdx.x;
    if (i >= n4) return;
    float4 v = ((const float4*)src)[i];
    __half2* d = (__half2*)dst;
    d[2 * i + 0] = __floats2half2_rn(v.x, v.y);
    d[2 * i + 1] = __floats2half2_rn(v.z, v.w);
}

// ---------------------------------------------------------------------------
// RoPE trig table with double-precision range reduction.
// ---------------------------------------------------------------------------
__global__ __launch_bounds__(256) void trig_kernel(const float* __restrict__ freqs) {
    int idx = blockIdx.x * blockDim.x + threadIdx.x;
    if (idx >= SEQ * 64) return;
    double a = (double)freqs[idx];
    double s, c;
    sincos(a, &s, &c);
    g_trig[idx * 2 + 0] = (float)c;
    g_trig[idx * 2 + 1] = (float)s;
}

// ---------------------------------------------------------------------------
// fp16 tensor-core GEMM, multi-output over blockIdx.z (R7 structure):
//   C_z[M,N] = A[M,K] @ W_z[N,K]^T + bias_z[N]
// BM=BN=128, BK=16, 256 threads (8 warps 4m x 2n), warp tile 32x64.
// Register-prefetch double buffer; smem stride 24 halfs (bank-conflict-free).
// ---------------------------------------------------------------------------
#define GSH 24

template <int HALF_OUT>
__global__ __launch_bounds__(256, 2) void gemm_h_kernel(
    const __half* __restrict__ A,
    const __half* __restrict__ W0, const __half* __restrict__ W1,
    const __half* __restrict__ W2,
    const float* __restrict__ b0p, const float* __restrict__ b1p,
    const float* __restrict__ b2p,
    void* C0, void* C1, void* C2)
{
    __shared__ __align__(16) __half As[2][128 * GSH];
    __shared__ __align__(16) __half Ws[2][128 * GSH];

    const int z = blockIdx.z;
    const __half* W   = (z == 0) ? W0  : (z == 1) ? W1  : W2;
    const float* bias = (z == 0) ? b0p : (z == 1) ? b1p : b2p;
    void* C           = (z == 0) ? C0  : (z == 1) ? C1  : C2;

    const int t    = threadIdx.x;
    const int lane = t & 31;
    const int warp = t >> 5;
    const int wm   = warp >> 1;     // 0..3
    const int wn   = warp & 1;      // 0..1
    const int bm   = blockIdx.y * 128;
    const int bn   = blockIdx.x * 128;

    const int lrow = t >> 1;            // 0..127
    const int lc8  = (t & 1) * 8;       // 0 or 8

    const __half* Ap = A + (size_t)(bm + lrow) * DIM + lc8;
    const __half* Wp = W + (size_t)(bn + lrow) * DIM + lc8;

    float c[2][8][4];
#pragma unroll
    for (int mt = 0; mt < 2; mt++)
#pragma unroll
        for (int nt = 0; nt < 8; nt++)
#pragma unroll
            for (int j = 0; j < 4; j++) c[mt][nt][j] = 0.f;

    const int KITERS = DIM / 16;   // 96

    uint4 pa = *(const uint4*)Ap;
    uint4 pw = *(const uint4*)Wp;
    *(uint4*)&As[0][lrow * GSH + lc8] = pa;
    *(uint4*)&Ws[0][lrow * GSH + lc8] = pw;
    __syncthreads();

    const int r0  = lane >> 2;
    const int kq  = lane & 3;
    const int r_a = wm * 32 + r0;
    const int r_b = wn * 64 + r0;

    for (int it = 0; it < KITERS; ++it) {
        const int cur = it & 1;
        if (it + 1 < KITERS) {
            pa = *(const uint4*)(Ap + (it + 1) * 16);
            pw = *(const uint4*)(Wp + (it + 1) * 16);
        }

        const __half* as = As[cur];
        const __half* ws = Ws[cur];

        unsigned a[2][4];
#pragma unroll
        for (int mt = 0; mt < 2; ++mt) {
            int r = r_a + mt * 16;
            a[mt][0] = ld32h(&as[r * GSH + 2 * kq]);
            a[mt][1] = ld32h(&as[(r + 8) * GSH + 2 * kq]);
            a[mt][2] = ld32h(&as[r * GSH + 2 * kq + 8]);
            a[mt][3] = ld32h(&as[(r + 8) * GSH + 2 * kq + 8]);
        }
#pragma unroll
        for (int nt = 0; nt < 8; ++nt) {
            int n = r_b + nt * 8;
            unsigned bb0 = ld32h(&ws[n * GSH + 2 * kq]);
            unsigned bb1 = ld32h(&ws[n * GSH + 2 * kq + 8]);
            mma_f16(c[0][nt], a[0], bb0, bb1);
            mma_f16(c[1][nt], a[1], bb0, bb1);
        }

        if (it + 1 < KITERS) {
            *(uint4*)&As[cur ^ 1][lrow * GSH + lc8] = pa;
            *(uint4*)&Ws[cur ^ 1][lrow * GSH + lc8] = pw;
        }
        __syncthreads();
    }

    // Epilogue: bias + store
#pragma unroll
    for (int mt = 0; mt < 2; ++mt) {
#pragma unroll
        for (int nt = 0; nt < 8; ++nt) {
            int row = bm + wm * 32 + mt * 16 + r0;
            int col = bn + wn * 64 + nt * 8 + 2 * kq;
            float bb0 = bias[col], bb1 = bias[col + 1];
            float v0 = c[mt][nt][0] + bb0, v1 = c[mt][nt][1] + bb1;
            float v2 = c[mt][nt][2] + bb0, v3 = c[mt][nt][3] + bb1;
            if (HALF_OUT) {
                __half2* Ch = (__half2*)C;
                Ch[((size_t)row * DIM + col) >> 1]       = __floats2half2_rn(v0, v1);
                Ch[((size_t)(row + 8) * DIM + col) >> 1] = __floats2half2_rn(v2, v3);
            } else {
                float* Cf = (float*)C;
                *(float2*)&Cf[(size_t)row * DIM + col]       = make_float2(v0, v1);
                *(float2*)&Cf[(size_t)(row + 8) * DIM + col] = make_float2(v2, v3);
            }
        }
    }
}

// ---------------------------------------------------------------------------
// Fused RMSNorm+RoPE (y=0: q, y=1: k) AND V-transpose (y=2) in ONE launch.
// Shared buffers overlay in a 16-byte-aligned union.
// ---------------------------------------------------------------------------
struct __align__(16) NTShared {
    union {
        struct {
            float sh[DIM];
            float red[8];
            float s_r;
        } n;
        __half tile[64][80];
    } u;
};

__global__ __launch_bounds__(256) void norm_and_transpose_kernel(
    __half* __restrict__ Xq, __half* __restrict__ Xk,
    const float* __restrict__ gqv, const float* __restrict__ gkv)
{
    __shared__ NTShared S;

    const int t = threadIdx.x;

    if (blockIdx.y == 2) {
        // ---- V transpose: g_vh[s][h*128+d] -> g_vt[h][d][s] ----
        const int bx = blockIdx.x;
        if (bx >= (SEQ / 64) * 2 * NHEADS) return;
        const int sblk = bx % (SEQ / 64);
        const int hz   = bx / (SEQ / 64);       // 0..23
        const int h    = hz >> 1;
        const int d0   = (hz & 1) * 64;
        const int s0   = sblk * 64;

        for (int i = t; i < 512; i += 256) {
            int r = i >> 3, c8 = (i & 7) * 8;
            uint4 v = *(const uint4*)&g_vh[(size_t)(s0 + r) * DIM + h * HDIM + d0 + c8];
            *(uint4*)&S.u.tile[r][c8] = v;
        }
        __syncthreads();
        for (int i = t; i < 512; i += 256) {
            int r = i >> 3, c8 = (i & 7) * 8;
            __half tmp[8];
#pragma unroll
            for (int j = 0; j < 8; ++j) tmp[j] = S.u.tile[c8 + j][r];
            *(uint4*)&g_vt[(size_t)(h * HDIM + d0 + r) * SEQ + s0 + c8] = *(uint4*)tmp;
        }
        return;
    }

    // ---- RMSNorm + RoPE ----
    const int s = blockIdx.x;
    const int which = blockIdx.y;
    __half* X = which ? Xk : Xq;
    const float* g = which ? gkv : gqv;

    __half2* row = (__half2*)(X + (size_t)s * DIM);

    float ss = 0.f;
    for (int i = t; i < DIM / 2; i += 256) {
        float2 f = __half22float2(row[i]);
        S.u.n.sh[2 * i]     = f.x;
        S.u.n.sh[2 * i + 1] = f.y;
        ss += f.x * f.x + f.y * f.y;
    }
#pragma unroll
    for (int off = 16; off > 0; off >>= 1)
        ss += __shfl_xor_sync(0xFFFFFFFFu, ss, off);
    if ((t & 31) == 0) S.u.n.red[t >> 5] = ss;
    __syncthreads();
    if (t == 0) {
        float tot = 0.f;
#pragma unroll
        for (int w = 0; w < 8; w++) tot += S.u.n.red[w];
        S.u.n.s_r = rsqrtf(tot / (float)DIM + EPS);
    }
    __syncthreads();
    const float r = S.u.n.s_r;

    for (int p = t; p < DIM / 2; p += 256) {
        int j = p & 63;
        float c  = g_trig[((size_t)s * 64 + j) * 2 + 0];
        float sn = g_trig[((size_t)s * 64 + j) * 2 + 1];
        float v0 = S.u.n.sh[2 * p] * r * g[2 * p];
        float v1 = S.u.n.sh[2 * p + 1] * r * g[2 * p + 1];
        row[p] = __floats2half2_rn(v0 * c - v1 * sn, v0 * sn + v1 * c);
    }
}

// ---------------------------------------------------------------------------
// fp16 flash attention (R7 body) at 3 CTAs/SM (12 warps/SM latency hiding).
// 128 threads (4 warps), BQ=64 (16 rows/warp), BK=64.
// Q fragments in registers. K natural [key][d]; V via Vt [d][key].
// fp32 softmax and O accumulators. Output fp16.
// ---------------------------------------------------------------------------
#define KSH 136
#define VSH 72
#define PSH 72
#define FA_SMEM_BYTES ((64 * KSH + 128 * VSH + 64 * PSH) * 2)   // 45056

__global__ __launch_bounds__(128, 3) void flash_h_kernel(
    const __half* __restrict__ Q, const __half* __restrict__ Kg,
    const __half* __restrict__ Vt, __half* __restrict__ O)
{
    extern __shared__ __align__(16) __half smh[];
    __half* Ks = smh;                    // 64 x 136
    __half* Vs = Ks + 64 * KSH;          // 128 x 72 (d-major)
    __half* Ps = Vs + 128 * VSH;         // 64 x 72

    const int h    = blockIdx.y;
    const int qb   = blockIdx.x;
    const int t    = threadIdx.x;
    const int lane = t & 31;
    const int warp = t >> 5;
    const int r0   = lane >> 2;
    const int qc   = lane & 3;
    const float scale = 0.08838834764831845f;   // 1/sqrt(128)

    // ---- Stage Q tile into Ks, pull A-fragments to registers ----
    {
        const __half* src = Q + (size_t)(qb * 64) * DIM + h * HDIM;
        for (int i = t; i < 64 * 16; i += 128) {
            int r = i >> 4, c8 = (i & 15) * 8;
            *(uint4*)&Ks[r * KSH + c8] = *(const uint4*)&src[(size_t)r * DIM + c8];
        }
    }
    __syncthreads();

    unsigned qa[8][4];
    {
        const int rb = warp * 16 + r0;
#pragma unroll
        for (int kt = 0; kt < 8; ++kt) {
            int kc = kt * 16 + 2 * qc;
            qa[kt][0] = ld32h(&Ks[rb * KSH + kc]);
            qa[kt][1] = ld32h(&Ks[(rb + 8) * KSH + kc]);
            qa[kt][2] = ld32h(&Ks[rb * KSH + kc + 8]);
            qa[kt][3] = ld32h(&Ks[(rb + 8) * KSH + kc + 8]);
        }
    }
    __syncthreads();

    float o[16][4];
#pragma unroll
    for (int nt = 0; nt < 16; ++nt)
#pragma unroll
        for (int j = 0; j < 4; ++j) o[nt][j] = 0.f;

    float m0 = -1e30f, m1 = -1e30f, l0 = 0.f, l1 = 0.f;
    const int prow = warp * 16 + r0;

    for (int kb = 0; kb < SEQ / 64; ++kb) {
        __syncthreads();

        // ---- Stage K tile [64 keys][128 d] and Vt tile [128 d][64 keys] ----
        {
            const __half* ksrc = Kg + (size_t)(kb * 64) * DIM + h * HDIM;
            for (int i = t; i < 64 * 16; i += 128) {
                int r = i >> 4, c8 = (i & 15) * 8;
                *(uint4*)&Ks[r * KSH + c8] = *(const uint4*)&ksrc[(size_t)r * DIM + c8];
            }
            const __half* vsrc = Vt + (size_t)h * HDIM * SEQ + kb * 64;
            for (int i = t; i < 128 * 8; i += 128) {
                int r = i >> 3, c8 = (i & 7) * 8;
                *(uint4*)&Vs[r * VSH + c8] = *(const uint4*)&vsrc[(size_t)r * SEQ + c8];
            }
        }
        __syncthreads();

        // ---- S = Q @ K^T (per warp: 16 x 64) ----
        float s[8][4];
#pragma unroll
        for (int nt = 0; nt < 8; ++nt)
#pragma unroll
            for (int j = 0; j < 4; ++j) s[nt][j] = 0.f;

#pragma unroll
        for (int nt = 0; nt < 8; ++nt) {
            const int nb = (nt * 8 + r0) * KSH + 2 * qc;
#pragma unroll
            for (int kt = 0; kt < 8; ++kt) {
                unsigned b0 = ld32h(&Ks[nb + kt * 16]);
                unsigned b1 = ld32h(&Ks[nb + kt * 16 + 8]);
                mma_f16(s[nt], qa[kt], b0, b1);
            }
        }

        // ---- Online softmax ----
        float mx0 = -1e30f, mx1 = -1e30f;
#pragma unroll
        for (int nt = 0; nt < 8; ++nt) {
            mx0 = fmaxf(mx0, fmaxf(s[nt][0], s[nt][1]));
            mx1 = fmaxf(mx1, fmaxf(s[nt][2], s[nt][3]));
        }
        mx0 = fmaxf(mx0, __shfl_xor_sync(0xFFFFFFFFu, mx0, 1));
        mx0 = fmaxf(mx0, __shfl_xor_sync(0xFFFFFFFFu, mx0, 2));
        mx1 = fmaxf(mx1, __shfl_xor_sync(0xFFFFFFFFu, mx1, 1));
        mx1 = fmaxf(mx1, __shfl_xor_sync(0xFFFFFFFFu, mx1, 2));

        float nm0 = fmaxf(m0, mx0 * scale);
        float nm1 = fmaxf(m1, mx1 * scale);
        float corr0 = __expf(m0 - nm0);
        float corr1 = __expf(m1 - nm1);

        float sum0 = 0.f, sum1 = 0.f;
#pragma unroll
        for (int nt = 0; nt < 8; ++nt) {
            s[nt][0] = __expf(s[nt][0] * scale - nm0);
            s[nt][1] = __expf(s[nt][1] * scale - nm0);
            s[nt][2] = __expf(s[nt][2] * scale - nm1);
            s[nt][3] = __expf(s[nt][3] * scale - nm1);
            sum0 += s[nt][0] + s[nt][1];
            sum1 += s[nt][2] + s[nt][3];
        }
        sum0 += __shfl_xor_sync(0xFFFFFFFFu, sum0, 1);
        sum0 += __shfl_xor_sync(0xFFFFFFFFu, sum0, 2);
        sum1 += __shfl_xor_sync(0xFFFFFFFFu, sum1, 1);
        sum1 += __shfl_xor_sync(0xFFFFFFFFu, sum1, 2);

        l0 = l0 * corr0 + sum0;
        l1 = l1 * corr1 + sum1;
        m0 = nm0;
        m1 = nm1;

#pragma unroll
        for (int nt = 0; nt < 16; ++nt) {
            o[nt][0] *= corr0; o[nt][1] *= corr0;
            o[nt][2] *= corr1; o[nt][3] *= corr1;
        }

        // ---- P -> smem fp16 (warp-local rows) ----
#pragma unroll
        for (int nt = 0; nt < 8; ++nt) {
            int pc = nt * 8 + 2 * qc;
            *(__half2*)&Ps[prow * PSH + pc] = __floats2half2_rn(s[nt][0], s[nt][1]);
            *(__half2*)&Ps[(prow + 8) * PSH + pc] = __floats2half2_rn(s[nt][2], s[nt][3]);
        }
        __syncwarp();

        // ---- O += P @ V (Vt d-major: each B-frag = one LDS.32) ----
#pragma unroll
        for (int kt = 0; kt < 4; ++kt) {
            unsigned a[4];
            int kc = kt * 16 + 2 * qc;
            a[0] = ld32h(&Ps[prow * PSH + kc]);
            a[1] = ld32h(&Ps[(prow + 8) * PSH + kc]);
            a[2] = ld32h(&Ps[prow * PSH + kc + 8]);
            a[3] = ld32h(&Ps[(prow + 8) * PSH + kc + 8]);
#pragma unroll
            for (int nt = 0; nt < 16; ++nt) {
                const int nb = (nt * 8 + r0) * VSH + kt * 16 + 2 * qc;
                unsigned b0 = ld32h(&Vs[nb]);
                unsigned b1 = ld32h(&Vs[nb + 8]);
                mma_f16(o[nt], a, b0, b1);
            }
        }
    }

    // ---- Epilogue: normalize, fp16 store ----
    float inv0 = 1.f / l0, inv1 = 1.f / l1;
    int grow = qb * 64 + warp * 16 + r0;
#pragma unroll
    for (int nt = 0; nt < 16; ++nt) {
        int col = h * HDIM + nt * 8 + 2 * qc;
        *(__half2*)&O[(size_t)grow * DIM + col] =
            __floats2half2_rn(o[nt][0] * inv0, o[nt][1] * inv0);
        *(__half2*)&O[(size_t)(grow + 8) * DIM + col] =
            __floats2half2_rn(o[nt][2] * inv1, o[nt][3] * inv1);
    }
}

// ---------------------------------------------------------------------------
// Launch
// ---------------------------------------------------------------------------
extern "C" void kernel_launch(void* const* d_in, const int* in_sizes, int n_in,
                              void* d_out, int out_size)
{
    const float* x     = (const float*)d_in[0];
    const float* freqs = (const float*)d_in[1];
    const float* Wq    = (const float*)d_in[2];
    const float* bq    = (const float*)d_in[3];
    const float* Wk    = (const float*)d_in[4];
    const float* bk    = (const float*)d_in[5];
    const float* Wv    = (const float*)d_in[6];
    const float* bv    = (const float*)d_in[7];
    const float* Wo    = (const float*)d_in[8];
    const float* bo    = (const float*)d_in[9];
    const float* gq    = (const float*)d_in[10];
    const float* gk    = (const float*)d_in[11];
    float* out = (float*)d_out;

    __half *xh, *qh, *kh, *vh, *attnh, *wqh, *wkh, *wvh, *woh, *vt;
    cudaGetSymbolAddress((void**)&xh,    g_xh);
    cudaGetSymbolAddress((void**)&qh,    g_qh);
    cudaGetSymbolAddress((void**)&kh,    g_kh);
    cudaGetSymbolAddress((void**)&vh,    g_vh);
    cudaGetSymbolAddress((void**)&attnh, g_attnh);
    cudaGetSymbolAddress((void**)&wqh,   g_wqh);
    cudaGetSymbolAddress((void**)&wkh,   g_wkh);
    cudaGetSymbolAddress((void**)&wvh,   g_wvh);
    cudaGetSymbolAddress((void**)&woh,   g_woh);
    cudaGetSymbolAddress((void**)&vt,    g_vt);

    cudaFuncSetAttribute(flash_h_kernel,
                         cudaFuncAttributeMaxDynamicSharedMemorySize, FA_SMEM_BYTES);

    // Prep: trig + fp16 conversion (single fused launch).
    trig_kernel<<<(SEQ * 64 + 255) / 256, 256>>>(freqs);
    to_half_all_kernel<<<dim3(SEQ * DIM / 4 / 256, 5), 256>>>(x, Wq, Wk, Wv, Wo);

    // Fused Q/K/V projection (fp16 in/out).
    dim3 qkv_grid(DIM / 128, SEQ / 128, 3);
    gemm_h_kernel<1><<<qkv_grid, 256>>>(
        xh, wqh, wkh, wvh, bq, bk, bv, qh, kh, vh);

    // RMSNorm+RoPE (q,k) and V transpose in one launch.
    norm_and_transpose_kernel<<<dim3(SEQ, 3), 256>>>(qh, kh, gq, gk);

    // Flash attention: BQ=64, 4 warps, 3 CTAs/SM.
    flash_h_kernel<<<dim3(SEQ / 64, NHEADS), 128, FA_SMEM_BYTES>>>(qh, kh, vt, attnh);

    // Output projection (fp32 out).
    dim3 o_grid(DIM / 128, SEQ / 128, 1);
    gemm_h_kernel<0><<<o_grid, 256>>>(
        attnh, woh, woh, woh, bo, bo, bo, out, out, out);
}

// round 12
// speedup vs baseline: 1.3879x; 1.3879x over previous
#include <cuda_runtime.h>
#include <cuda_fp16.h>
#include <math.h>
#include <stdint.h>

// ---------------------------------------------------------------------------
// Problem constants (B=1, S=4096, DIM=1536, HEADS=12, HEAD_DIM=128)
// ---------------------------------------------------------------------------
#define SEQ    4096
#define DIM    1536
#define NHEADS 12
#define HDIM   128
#define EPS    1e-6f

// Scratch (allocation-free rule: __device__ globals)
__device__ __half g_xh[SEQ * DIM];
__device__ __half g_qh[SEQ * DIM];
__device__ __half g_kh[SEQ * DIM];
__device__ __half g_vh[SEQ * DIM];
__device__ __half g_attnh[SEQ * DIM];
__device__ __half g_wqh[DIM * DIM];
__device__ __half g_wkh[DIM * DIM];
__device__ __half g_wvh[DIM * DIM];
__device__ __half g_woh[DIM * DIM];
__device__ __half g_vt[NHEADS * HDIM * SEQ];   // V transposed: [h][d][s]
__device__ float  g_trig[SEQ * 64 * 2];        // cos,sin per (pos, pair)

// ---------------------------------------------------------------------------
// Helpers
// ---------------------------------------------------------------------------
__device__ __forceinline__ unsigned ld32h(const __half* p) {
    return *(const unsigned*)p;
}

// D += A*B, m16n8k16, fp16 inputs, f32 accumulate
__device__ __forceinline__ void mma_f16(float* d, const unsigned* a,
                                        unsigned b0, unsigned b1) {
    asm volatile(
        "mma.sync.aligned.m16n8k16.row.col.f32.f16.f16.f32 "
        "{%0,%1,%2,%3}, {%4,%5,%6,%7}, {%8,%9}, {%0,%1,%2,%3};\n"
        : "+f"(d[0]), "+f"(d[1]), "+f"(d[2]), "+f"(d[3])
        : "r"(a[0]), "r"(a[1]), "r"(a[2]), "r"(a[3]), "r"(b0), "r"(b1));
}

__device__ __forceinline__ void cp16(void* smem_dst, const void* gsrc) {
    unsigned s = (unsigned)__cvta_generic_to_shared(smem_dst);
    asm volatile("cp.async.cg.shared.global [%0], [%1], 16;\n" :: "r"(s), "l"(gsrc));
}
__device__ __forceinline__ void cp_commit() {
    asm volatile("cp.async.commit_group;\n");
}
template <int N>
__device__ __forceinline__ void cp_wait() {
    asm volatile("cp.async.wait_group %0;\n" :: "n"(N));
}

// ---------------------------------------------------------------------------
// Prep: fp32 -> fp16, 5 segments in one launch (y: 0=x, 1..4=Wq,Wk,Wv,Wo)
// ---------------------------------------------------------------------------
__global__ __launch_bounds__(256) void to_half_all_kernel(
    const float* __restrict__ x,  const float* __restrict__ Wq,
    const float* __restrict__ Wk, const float* __restrict__ Wv,
    const float* __restrict__ Wo)
{
    const int seg = blockIdx.y;
    const float* src;
    __half* dst;
    int n4;
    if (seg == 0)      { src = x;  dst = g_xh;  n4 = SEQ * DIM / 4; }
    else if (seg == 1) { src = Wq; dst = g_wqh; n4 = DIM * DIM / 4; }
    else if (seg == 2) { src = Wk; dst = g_wkh; n4 = DIM * DIM / 4; }
    else if (seg == 3) { src = Wv; dst = g_wvh; n4 = DIM * DIM / 4; }
    else               { src = Wo; dst = g_woh; n4 = DIM * DIM / 4; }

    int i = blockIdx.x * blockDim.x + threadIdx.x;
    if (i >= n4) return;
    float4 v = ((const float4*)src)[i];
    __half2* d = (__half2*)dst;
    d[2 * i + 0] = __floats2half2_rn(v.x, v.y);
    d[2 * i + 1] = __floats2half2_rn(v.z, v.w);
}

// ---------------------------------------------------------------------------
// RoPE trig table with double-precision range reduction.
// ---------------------------------------------------------------------------
__global__ __launch_bounds__(256) void trig_kernel(const float* __restrict__ freqs) {
    int idx = blockIdx.x * blockDim.x + threadIdx.x;
    if (idx >= SEQ * 64) return;
    double a = (double)freqs[idx];
    double s, c;
    sincos(a, &s, &c);
    g_trig[idx * 2 + 0] = (float)c;
    g_trig[idx * 2 + 1] = (float)s;
}

// ---------------------------------------------------------------------------
// fp16 tensor-core GEMM, multi-output over blockIdx.z (R7 structure):
//   C_z[M,N] = A[M,K] @ W_z[N,K]^T + bias_z[N]
// BM=BN=128, BK=16, 256 threads (8 warps 4m x 2n), warp tile 32x64.
// Register-prefetch double buffer; smem stride 24 halfs (bank-conflict-free).
// ---------------------------------------------------------------------------
#define GSH 24

template <int HALF_OUT>
__global__ __launch_bounds__(256, 2) void gemm_h_kernel(
    const __half* __restrict__ A,
    const __half* __restrict__ W0, const __half* __restrict__ W1,
    const __half* __restrict__ W2,
    const float* __restrict__ b0p, const float* __restrict__ b1p,
    const float* __restrict__ b2p,
    void* C0, void* C1, void* C2)
{
    __shared__ __align__(16) __half As[2][128 * GSH];
    __shared__ __align__(16) __half Ws[2][128 * GSH];

    const int z = blockIdx.z;
    const __half* W   = (z == 0) ? W0  : (z == 1) ? W1  : W2;
    const float* bias = (z == 0) ? b0p : (z == 1) ? b1p : b2p;
    void* C           = (z == 0) ? C0  : (z == 1) ? C1  : C2;

    const int t    = threadIdx.x;
    const int lane = t & 31;
    const int warp = t >> 5;
    const int wm   = warp >> 1;     // 0..3
    const int wn   = warp & 1;      // 0..1
    const int bm   = blockIdx.y * 128;
    const int bn   = blockIdx.x * 128;

    const int lrow = t >> 1;            // 0..127
    const int lc8  = (t & 1) * 8;       // 0 or 8

    const __half* Ap = A + (size_t)(bm + lrow) * DIM + lc8;
    const __half* Wp = W + (size_t)(bn + lrow) * DIM + lc8;

    float c[2][8][4];
#pragma unroll
    for (int mt = 0; mt < 2; mt++)
#pragma unroll
        for (int nt = 0; nt < 8; nt++)
#pragma unroll
            for (int j = 0; j < 4; j++) c[mt][nt][j] = 0.f;

    const int KITERS = DIM / 16;   // 96

    uint4 pa = *(const uint4*)Ap;
    uint4 pw = *(const uint4*)Wp;
    *(uint4*)&As[0][lrow * GSH + lc8] = pa;
    *(uint4*)&Ws[0][lrow * GSH + lc8] = pw;
    __syncthreads();

    const int r0  = lane >> 2;
    const int kq  = lane & 3;
    const int r_a = wm * 32 + r0;
    const int r_b = wn * 64 + r0;

    for (int it = 0; it < KITERS; ++it) {
        const int cur = it & 1;
        if (it + 1 < KITERS) {
            pa = *(const uint4*)(Ap + (it + 1) * 16);
            pw = *(const uint4*)(Wp + (it + 1) * 16);
        }

        const __half* as = As[cur];
        const __half* ws = Ws[cur];

        unsigned a[2][4];
#pragma unroll
        for (int mt = 0; mt < 2; ++mt) {
            int r = r_a + mt * 16;
            a[mt][0] = ld32h(&as[r * GSH + 2 * kq]);
            a[mt][1] = ld32h(&as[(r + 8) * GSH + 2 * kq]);
            a[mt][2] = ld32h(&as[r * GSH + 2 * kq + 8]);
            a[mt][3] = ld32h(&as[(r + 8) * GSH + 2 * kq + 8]);
        }
#pragma unroll
        for (int nt = 0; nt < 8; ++nt) {
            int n = r_b + nt * 8;
            unsigned bb0 = ld32h(&ws[n * GSH + 2 * kq]);
            unsigned bb1 = ld32h(&ws[n * GSH + 2 * kq + 8]);
            mma_f16(c[0][nt], a[0], bb0, bb1);
            mma_f16(c[1][nt], a[1], bb0, bb1);
        }

        if (it + 1 < KITERS) {
            *(uint4*)&As[cur ^ 1][lrow * GSH + lc8] = pa;
            *(uint4*)&Ws[cur ^ 1][lrow * GSH + lc8] = pw;
        }
        __syncthreads();
    }

    // Epilogue: bias + store
#pragma unroll
    for (int mt = 0; mt < 2; ++mt) {
#pragma unroll
        for (int nt = 0; nt < 8; ++nt) {
            int row = bm + wm * 32 + mt * 16 + r0;
            int col = bn + wn * 64 + nt * 8 + 2 * kq;
            float bb0 = bias[col], bb1 = bias[col + 1];
            float v0 = c[mt][nt][0] + bb0, v1 = c[mt][nt][1] + bb1;
            float v2 = c[mt][nt][2] + bb0, v3 = c[mt][nt][3] + bb1;
            if (HALF_OUT) {
                __half2* Ch = (__half2*)C;
                Ch[((size_t)row * DIM + col) >> 1]       = __floats2half2_rn(v0, v1);
                Ch[((size_t)(row + 8) * DIM + col) >> 1] = __floats2half2_rn(v2, v3);
            } else {
                float* Cf = (float*)C;
                *(float2*)&Cf[(size_t)row * DIM + col]       = make_float2(v0, v1);
                *(float2*)&Cf[(size_t)(row + 8) * DIM + col] = make_float2(v2, v3);
            }
        }
    }
}

// ---------------------------------------------------------------------------
// Fused RMSNorm+RoPE (y=0: q, y=1: k) AND V-transpose (y=2) in ONE launch.
// Shared buffers overlay in a 16-byte-aligned union.
// ---------------------------------------------------------------------------
struct __align__(16) NTShared {
    union {
        struct {
            float sh[DIM];
            float red[8];
            float s_r;
        } n;
        __half tile[64][80];
    } u;
};

__global__ __launch_bounds__(256) void norm_and_transpose_kernel(
    __half* __restrict__ Xq, __half* __restrict__ Xk,
    const float* __restrict__ gqv, const float* __restrict__ gkv)
{
    __shared__ NTShared S;

    const int t = threadIdx.x;

    if (blockIdx.y == 2) {
        // ---- V transpose: g_vh[s][h*128+d] -> g_vt[h][d][s] ----
        const int bx = blockIdx.x;
        if (bx >= (SEQ / 64) * 2 * NHEADS) return;
        const int sblk = bx % (SEQ / 64);
        const int hz   = bx / (SEQ / 64);       // 0..23
        const int h    = hz >> 1;
        const int d0   = (hz & 1) * 64;
        const int s0   = sblk * 64;

        for (int i = t; i < 512; i += 256) {
            int r = i >> 3, c8 = (i & 7) * 8;
            uint4 v = *(const uint4*)&g_vh[(size_t)(s0 + r) * DIM + h * HDIM + d0 + c8];
            *(uint4*)&S.u.tile[r][c8] = v;
        }
        __syncthreads();
        for (int i = t; i < 512; i += 256) {
            int r = i >> 3, c8 = (i & 7) * 8;
            __half tmp[8];
#pragma unroll
            for (int j = 0; j < 8; ++j) tmp[j] = S.u.tile[c8 + j][r];
            *(uint4*)&g_vt[(size_t)(h * HDIM + d0 + r) * SEQ + s0 + c8] = *(uint4*)tmp;
        }
        return;
    }

    // ---- RMSNorm + RoPE ----
    const int s = blockIdx.x;
    const int which = blockIdx.y;
    __half* X = which ? Xk : Xq;
    const float* g = which ? gkv : gqv;

    __half2* row = (__half2*)(X + (size_t)s * DIM);

    float ss = 0.f;
    for (int i = t; i < DIM / 2; i += 256) {
        float2 f = __half22float2(row[i]);
        S.u.n.sh[2 * i]     = f.x;
        S.u.n.sh[2 * i + 1] = f.y;
        ss += f.x * f.x + f.y * f.y;
    }
#pragma unroll
    for (int off = 16; off > 0; off >>= 1)
        ss += __shfl_xor_sync(0xFFFFFFFFu, ss, off);
    if ((t & 31) == 0) S.u.n.red[t >> 5] = ss;
    __syncthreads();
    if (t == 0) {
        float tot = 0.f;
#pragma unroll
        for (int w = 0; w < 8; w++) tot += S.u.n.red[w];
        S.u.n.s_r = rsqrtf(tot / (float)DIM + EPS);
    }
    __syncthreads();
    const float r = S.u.n.s_r;

    for (int p = t; p < DIM / 2; p += 256) {
        int j = p & 63;
        float c  = g_trig[((size_t)s * 64 + j) * 2 + 0];
        float sn = g_trig[((size_t)s * 64 + j) * 2 + 1];
        float v0 = S.u.n.sh[2 * p] * r * g[2 * p];
        float v1 = S.u.n.sh[2 * p + 1] * r * g[2 * p + 1];
        row[p] = __floats2half2_rn(v0 * c - v1 * sn, v0 * sn + v1 * c);
    }
}

// ---------------------------------------------------------------------------
// fp16 flash attention, cp.async double-buffered K/V (R10 compute body).
// 128 threads (4 warps), BQ=64 (16 rows/warp), BK=64, 2 CTAs/SM.
// Q fragments in registers. K natural [key][d]; V via Vt [d][key].
// fp32 softmax and O accumulators. Output fp16.
// ---------------------------------------------------------------------------
#define KSH 136
#define VSH 72
#define PSH 72
// 2 K buffers + 2 V buffers + Ps
#define FA_SMEM_BYTES ((2 * 64 * KSH + 2 * 128 * VSH + 64 * PSH) * 2)   // 80896

__global__ __launch_bounds__(128, 2) void flash_h_kernel(
    const __half* __restrict__ Q, const __half* __restrict__ Kg,
    const __half* __restrict__ Vt, __half* __restrict__ O)
{
    extern __shared__ __align__(16) __half smh[];
    __half* Kb[2];
    __half* Vb[2];
    Kb[0] = smh;
    Kb[1] = Kb[0] + 64 * KSH;
    Vb[0] = Kb[1] + 64 * KSH;
    Vb[1] = Vb[0] + 128 * VSH;
    __half* Ps = Vb[1] + 128 * VSH;

    const int h    = blockIdx.y;
    const int qb   = blockIdx.x;
    const int t    = threadIdx.x;
    const int lane = t & 31;
    const int warp = t >> 5;
    const int r0   = lane >> 2;
    const int qc   = lane & 3;
    const float scale = 0.08838834764831845f;   // 1/sqrt(128)

    // ---- Stage Q tile into Kb[0], pull A-fragments to registers ----
    {
        const __half* src = Q + (size_t)(qb * 64) * DIM + h * HDIM;
        for (int i = t; i < 64 * 16; i += 128) {
            int r = i >> 4, c8 = (i & 15) * 8;
            *(uint4*)&Kb[0][r * KSH + c8] = *(const uint4*)&src[(size_t)r * DIM + c8];
        }
    }
    __syncthreads();

    unsigned qa[8][4];
    {
        const int rb = warp * 16 + r0;
#pragma unroll
        for (int kt = 0; kt < 8; ++kt) {
            int kc = kt * 16 + 2 * qc;
            qa[kt][0] = ld32h(&Kb[0][rb * KSH + kc]);
            qa[kt][1] = ld32h(&Kb[0][(rb + 8) * KSH + kc]);
            qa[kt][2] = ld32h(&Kb[0][rb * KSH + kc + 8]);
            qa[kt][3] = ld32h(&Kb[0][(rb + 8) * KSH + kc + 8]);
        }
    }
    __syncthreads();

    // ---- cp.async stage: K/V tile kb into buffer kb&1 ----
    auto stage_kv = [&](int kb) {
        __half* dk = Kb[kb & 1];
        __half* dv = Vb[kb & 1];
        const __half* ksrc = Kg + (size_t)(kb * 64) * DIM + h * HDIM;
        const __half* vsrc = Vt + (size_t)h * HDIM * SEQ + kb * 64;
        // K: 64 rows x 16 chunks (8 halfs) = 1024 cp16
        for (int i = t; i < 64 * 16; i += 128) {
            int r = i >> 4, c8 = (i & 15) * 8;
            cp16(&dk[r * KSH + c8], &ksrc[(size_t)r * DIM + c8]);
        }
        // V: 128 rows x 8 chunks (8 halfs) = 1024 cp16
        for (int i = t; i < 128 * 8; i += 128) {
            int r = i >> 3, c8 = (i & 7) * 8;
            cp16(&dv[r * VSH + c8], &vsrc[(size_t)r * SEQ + c8]);
        }
        cp_commit();
    };

    stage_kv(0);
    stage_kv(1);

    float o[16][4];
#pragma unroll
    for (int nt = 0; nt < 16; ++nt)
#pragma unroll
        for (int j = 0; j < 4; ++j) o[nt][j] = 0.f;

    float m0 = -1e30f, m1 = -1e30f, l0 = 0.f, l1 = 0.f;
    const int prow = warp * 16 + r0;
    const int NT = SEQ / 64;   // 64

    for (int kb = 0; kb < NT; ++kb) {
        if (kb + 1 < NT) cp_wait<1>(); else cp_wait<0>();
        __syncthreads();

        const __half* Ks = Kb[kb & 1];
        const __half* Vs = Vb[kb & 1];

        // ---- S = Q @ K^T (per warp: 16 x 64) ----
        float s[8][4];
#pragma unroll
        for (int nt = 0; nt < 8; ++nt)
#pragma unroll
            for (int j = 0; j < 4; ++j) s[nt][j] = 0.f;

#pragma unroll
        for (int nt = 0; nt < 8; ++nt) {
            const int nb = (nt * 8 + r0) * KSH + 2 * qc;
#pragma unroll
            for (int kt = 0; kt < 8; ++kt) {
                unsigned b0 = ld32h(&Ks[nb + kt * 16]);
                unsigned b1 = ld32h(&Ks[nb + kt * 16 + 8]);
                mma_f16(s[nt], qa[kt], b0, b1);
            }
        }

        // ---- Online softmax ----
        float mx0 = -1e30f, mx1 = -1e30f;
#pragma unroll
        for (int nt = 0; nt < 8; ++nt) {
            mx0 = fmaxf(mx0, fmaxf(s[nt][0], s[nt][1]));
            mx1 = fmaxf(mx1, fmaxf(s[nt][2], s[nt][3]));
        }
        mx0 = fmaxf(mx0, __shfl_xor_sync(0xFFFFFFFFu, mx0, 1));
        mx0 = fmaxf(mx0, __shfl_xor_sync(0xFFFFFFFFu, mx0, 2));
        mx1 = fmaxf(mx1, __shfl_xor_sync(0xFFFFFFFFu, mx1, 1));
        mx1 = fmaxf(mx1, __shfl_xor_sync(0xFFFFFFFFu, mx1, 2));

        float nm0 = fmaxf(m0, mx0 * scale);
        float nm1 = fmaxf(m1, mx1 * scale);
        float corr0 = __expf(m0 - nm0);
        float corr1 = __expf(m1 - nm1);

        float sum0 = 0.f, sum1 = 0.f;
#pragma unroll
        for (int nt = 0; nt < 8; ++nt) {
            s[nt][0] = __expf(s[nt][0] * scale - nm0);
            s[nt][1] = __expf(s[nt][1] * scale - nm0);
            s[nt][2] = __expf(s[nt][2] * scale - nm1);
            s[nt][3] = __expf(s[nt][3] * scale - nm1);
            sum0 += s[nt][0] + s[nt][1];
            sum1 += s[nt][2] + s[nt][3];
        }
        sum0 += __shfl_xor_sync(0xFFFFFFFFu, sum0, 1);
        sum0 += __shfl_xor_sync(0xFFFFFFFFu, sum0, 2);
        sum1 += __shfl_xor_sync(0xFFFFFFFFu, sum1, 1);
        sum1 += __shfl_xor_sync(0xFFFFFFFFu, sum1, 2);

        l0 = l0 * corr0 + sum0;
        l1 = l1 * corr1 + sum1;
        m0 = nm0;
        m1 = nm1;

#pragma unroll
        for (int nt = 0; nt < 16; ++nt) {
            o[nt][0] *= corr0; o[nt][1] *= corr0;
            o[nt][2] *= corr1; o[nt][3] *= corr1;
        }

        // ---- P -> smem fp16 (warp-local rows) ----
#pragma unroll
        for (int nt = 0; nt < 8; ++nt) {
            int pc = nt * 8 + 2 * qc;
            *(__half2*)&Ps[prow * PSH + pc] = __floats2half2_rn(s[nt][0], s[nt][1]);
            *(__half2*)&Ps[(prow + 8) * PSH + pc] = __floats2half2_rn(s[nt][2], s[nt][3]);
        }
        __syncwarp();

        // ---- O += P @ V (Vt d-major: each B-frag = one LDS.32) ----
#pragma unroll
        for (int kt = 0; kt < 4; ++kt) {
            unsigned a[4];
            int kc = kt * 16 + 2 * qc;
            a[0] = ld32h(&Ps[prow * PSH + kc]);
            a[1] = ld32h(&Ps[(prow + 8) * PSH + kc]);
            a[2] = ld32h(&Ps[prow * PSH + kc + 8]);
            a[3] = ld32h(&Ps[(prow + 8) * PSH + kc + 8]);
#pragma unroll
            for (int nt = 0; nt < 16; ++nt) {
                const int nb = (nt * 8 + r0) * VSH + kt * 16 + 2 * qc;
                unsigned b0 = ld32h(&Vs[nb]);
                unsigned b1 = ld32h(&Vs[nb + 8]);
                mma_f16(o[nt], a, b0, b1);
            }
        }

        __syncthreads();                 // all warps done reading buffer kb&1
        if (kb + 2 < NT) stage_kv(kb + 2);
    }

    // ---- Epilogue: normalize, fp16 store ----
    float inv0 = 1.f / l0, inv1 = 1.f / l1;
    int grow = qb * 64 + warp * 16 + r0;
#pragma unroll
    for (int nt = 0; nt < 16; ++nt) {
        int col = h * HDIM + nt * 8 + 2 * qc;
        *(__half2*)&O[(size_t)grow * DIM + col] =
            __floats2half2_rn(o[nt][0] * inv0, o[nt][1] * inv0);
        *(__half2*)&O[(size_t)(grow + 8) * DIM + col] =
            __floats2half2_rn(o[nt][2] * inv1, o[nt][3] * inv1);
    }
}

// ---------------------------------------------------------------------------
// Launch
// ---------------------------------------------------------------------------
extern "C" void kernel_launch(void* const* d_in, const int* in_sizes, int n_in,
                              void* d_out, int out_size)
{
    const float* x     = (const float*)d_in[0];
    const float* freqs = (const float*)d_in[1];
    const float* Wq    = (const float*)d_in[2];
    const float* bq    = (const float*)d_in[3];
    const float* Wk    = (const float*)d_in[4];
    const float* bk    = (const float*)d_in[5];
    const float* Wv    = (const float*)d_in[6];
    const float* bv    = (const float*)d_in[7];
    const float* Wo    = (const float*)d_in[8];
    const float* bo    = (const float*)d_in[9];
    const float* gq    = (const float*)d_in[10];
    const float* gk    = (const float*)d_in[11];
    float* out = (float*)d_out;

    __half *xh, *qh, *kh, *vh, *attnh, *wqh, *wkh, *wvh, *woh, *vt;
    cudaGetSymbolAddress((void**)&xh,    g_xh);
    cudaGetSymbolAddress((void**)&qh,    g_qh);
    cudaGetSymbolAddress((void**)&kh,    g_kh);
    cudaGetSymbolAddress((void**)&vh,    g_vh);
    cudaGetSymbolAddress((void**)&attnh, g_attnh);
    cudaGetSymbolAddress((void**)&wqh,   g_wqh);
    cudaGetSymbolAddress((void**)&wkh,   g_wkh);
    cudaGetSymbolAddress((void**)&wvh,   g_wvh);
    cudaGetSymbolAddress((void**)&woh,   g_woh);
    cudaGetSymbolAddress((void**)&vt,    g_vt);

    cudaFuncSetAttribute(flash_h_kernel,
                         cudaFuncAttributeMaxDynamicSharedMemorySize, FA_SMEM_BYTES);

    // Prep: trig + fp16 conversion (single fused launch).
    trig_kernel<<<(SEQ * 64 + 255) / 256, 256>>>(freqs);
    to_half_all_kernel<<<dim3(SEQ * DIM / 4 / 256, 5), 256>>>(x, Wq, Wk, Wv, Wo);

    // Fused Q/K/V projection (fp16 in/out).
    dim3 qkv_grid(DIM / 128, SEQ / 128, 3);
    gemm_h_kernel<1><<<qkv_grid, 256>>>(
        xh, wqh, wkh, wvh, bq, bk, bv, qh, kh, vh);

    // RMSNorm+RoPE (q,k) and V transpose in one launch.
    norm_and_transpose_kernel<<<dim3(SEQ, 3), 256>>>(qh, kh, gq, gk);

    // Flash attention: BQ=64, 4 warps, 2 CTAs/SM, cp.async double buffer.
    flash_h_kernel<<<dim3(SEQ / 64, NHEADS), 128, FA_SMEM_BYTES>>>(qh, kh, vt, attnh);

    // Output projection (fp32 out).
    dim3 o_grid(DIM / 128, SEQ / 128, 1);
    gemm_h_kernel<0><<<o_grid, 256>>>(
        attnh, woh, woh, woh, bo, bo, bo, out, out, out);
}

// round 13
// speedup vs baseline: 1.4680x; 1.0577x over previous
#include <cuda_runtime.h>
#include <cuda_fp16.h>
#include <math.h>
#include <stdint.h>

// ---------------------------------------------------------------------------
// Problem constants (B=1, S=4096, DIM=1536, HEADS=12, HEAD_DIM=128)
// ---------------------------------------------------------------------------
#define SEQ    4096
#define DIM    1536
#define NHEADS 12
#define HDIM   128
#define EPS    1e-6f

// Scratch (allocation-free rule: __device__ globals)
__device__ __half g_xh[SEQ * DIM];
__device__ __half g_qh[SEQ * DIM];
__device__ __half g_kh[SEQ * DIM];
__device__ __half g_vh[SEQ * DIM];
__device__ __half g_attnh[SEQ * DIM];
__device__ __half g_wqh[DIM * DIM];
__device__ __half g_wkh[DIM * DIM];
__device__ __half g_wvh[DIM * DIM];
__device__ __half g_woh[DIM * DIM];
__device__ __half g_vt[NHEADS * HDIM * SEQ];   // V transposed: [h][d][s]
__device__ float  g_trig[SEQ * 64 * 2];        // cos,sin per (pos, pair)

// ---------------------------------------------------------------------------
// Helpers
// ---------------------------------------------------------------------------
__device__ __forceinline__ unsigned ld32h(const __half* p) {
    return *(const unsigned*)p;
}

__device__ __forceinline__ unsigned packh2(float x, float y) {
    __half2 h = __floats2half2_rn(x, y);
    return *(unsigned*)&h;
}

// D += A*B, m16n8k16, fp16 inputs, f32 accumulate
__device__ __forceinline__ void mma_f16(float* d, const unsigned* a,
                                        unsigned b0, unsigned b1) {
    asm volatile(
        "mma.sync.aligned.m16n8k16.row.col.f32.f16.f16.f32 "
        "{%0,%1,%2,%3}, {%4,%5,%6,%7}, {%8,%9}, {%0,%1,%2,%3};\n"
        : "+f"(d[0]), "+f"(d[1]), "+f"(d[2]), "+f"(d[3])
        : "r"(a[0]), "r"(a[1]), "r"(a[2]), "r"(a[3]), "r"(b0), "r"(b1));
}

__device__ __forceinline__ void cp16(void* smem_dst, const void* gsrc) {
    unsigned s = (unsigned)__cvta_generic_to_shared(smem_dst);
    asm volatile("cp.async.cg.shared.global [%0], [%1], 16;\n" :: "r"(s), "l"(gsrc));
}
__device__ __forceinline__ void cp_commit() {
    asm volatile("cp.async.commit_group;\n");
}
template <int N>
__device__ __forceinline__ void cp_wait() {
    asm volatile("cp.async.wait_group %0;\n" :: "n"(N));
}

// ---------------------------------------------------------------------------
// Prep: fp32 -> fp16, 5 segments in one launch (y: 0=x, 1..4=Wq,Wk,Wv,Wo)
// ---------------------------------------------------------------------------
__global__ __launch_bounds__(256) void to_half_all_kernel(
    const float* __restrict__ x,  const float* __restrict__ Wq,
    const float* __restrict__ Wk, const float* __restrict__ Wv,
    const float* __restrict__ Wo)
{
    const int seg = blockIdx.y;
    const float* src;
    __half* dst;
    int n4;
    if (seg == 0)      { src = x;  dst = g_xh;  n4 = SEQ * DIM / 4; }
    else if (seg == 1) { src = Wq; dst = g_wqh; n4 = DIM * DIM / 4; }
    else if (seg == 2) { src = Wk; dst = g_wkh; n4 = DIM * DIM / 4; }
    else if (seg == 3) { src = Wv; dst = g_wvh; n4 = DIM * DIM / 4; }
    else               { src = Wo; dst = g_woh; n4 = DIM * DIM / 4; }

    int i = blockIdx.x * blockDim.x + threadIdx.x;
    if (i >= n4) return;
    float4 v = ((const float4*)src)[i];
    __half2* d = (__half2*)dst;
    d[2 * i + 0] = __floats2half2_rn(v.x, v.y);
    d[2 * i + 1] = __floats2half2_rn(v.z, v.w);
}

// ---------------------------------------------------------------------------
// RoPE trig table with double-precision range reduction.
// ---------------------------------------------------------------------------
__global__ __launch_bounds__(256) void trig_kernel(const float* __restrict__ freqs) {
    int idx = blockIdx.x * blockDim.x + threadIdx.x;
    if (idx >= SEQ * 64) return;
    double a = (double)freqs[idx];
    double s, c;
    sincos(a, &s, &c);
    g_trig[idx * 2 + 0] = (float)c;
    g_trig[idx * 2 + 1] = (float)s;
}

// ---------------------------------------------------------------------------
// fp16 tensor-core GEMM, multi-output over blockIdx.z (R7 structure):
//   C_z[M,N] = A[M,K] @ W_z[N,K]^T + bias_z[N]
// BM=BN=128, BK=16, 256 threads (8 warps 4m x 2n), warp tile 32x64.
// Register-prefetch double buffer; smem stride 24 halfs (bank-conflict-free).
// ---------------------------------------------------------------------------
#define GSH 24

template <int HALF_OUT>
__global__ __launch_bounds__(256, 2) void gemm_h_kernel(
    const __half* __restrict__ A,
    const __half* __restrict__ W0, const __half* __restrict__ W1,
    const __half* __restrict__ W2,
    const float* __restrict__ b0p, const float* __restrict__ b1p,
    const float* __restrict__ b2p,
    void* C0, void* C1, void* C2)
{
    __shared__ __align__(16) __half As[2][128 * GSH];
    __shared__ __align__(16) __half Ws[2][128 * GSH];

    const int z = blockIdx.z;
    const __half* W   = (z == 0) ? W0  : (z == 1) ? W1  : W2;
    const float* bias = (z == 0) ? b0p : (z == 1) ? b1p : b2p;
    void* C           = (z == 0) ? C0  : (z == 1) ? C1  : C2;

    const int t    = threadIdx.x;
    const int lane = t & 31;
    const int warp = t >> 5;
    const int wm   = warp >> 1;     // 0..3
    const int wn   = warp & 1;      // 0..1
    const int bm   = blockIdx.y * 128;
    const int bn   = blockIdx.x * 128;

    const int lrow = t >> 1;            // 0..127
    const int lc8  = (t & 1) * 8;       // 0 or 8

    const __half* Ap = A + (size_t)(bm + lrow) * DIM + lc8;
    const __half* Wp = W + (size_t)(bn + lrow) * DIM + lc8;

    float c[2][8][4];
#pragma unroll
    for (int mt = 0; mt < 2; mt++)
#pragma unroll
        for (int nt = 0; nt < 8; nt++)
#pragma unroll
            for (int j = 0; j < 4; j++) c[mt][nt][j] = 0.f;

    const int KITERS = DIM / 16;   // 96

    uint4 pa = *(const uint4*)Ap;
    uint4 pw = *(const uint4*)Wp;
    *(uint4*)&As[0][lrow * GSH + lc8] = pa;
    *(uint4*)&Ws[0][lrow * GSH + lc8] = pw;
    __syncthreads();

    const int r0  = lane >> 2;
    const int kq  = lane & 3;
    const int r_a = wm * 32 + r0;
    const int r_b = wn * 64 + r0;

    for (int it = 0; it < KITERS; ++it) {
        const int cur = it & 1;
        if (it + 1 < KITERS) {
            pa = *(const uint4*)(Ap + (it + 1) * 16);
            pw = *(const uint4*)(Wp + (it + 1) * 16);
        }

        const __half* as = As[cur];
        const __half* ws = Ws[cur];

        unsigned a[2][4];
#pragma unroll
        for (int mt = 0; mt < 2; ++mt) {
            int r = r_a + mt * 16;
            a[mt][0] = ld32h(&as[r * GSH + 2 * kq]);
            a[mt][1] = ld32h(&as[(r + 8) * GSH + 2 * kq]);
            a[mt][2] = ld32h(&as[r * GSH + 2 * kq + 8]);
            a[mt][3] = ld32h(&as[(r + 8) * GSH + 2 * kq + 8]);
        }
#pragma unroll
        for (int nt = 0; nt < 8; ++nt) {
            int n = r_b + nt * 8;
            unsigned bb0 = ld32h(&ws[n * GSH + 2 * kq]);
            unsigned bb1 = ld32h(&ws[n * GSH + 2 * kq + 8]);
            mma_f16(c[0][nt], a[0], bb0, bb1);
            mma_f16(c[1][nt], a[1], bb0, bb1);
        }

        if (it + 1 < KITERS) {
            *(uint4*)&As[cur ^ 1][lrow * GSH + lc8] = pa;
            *(uint4*)&Ws[cur ^ 1][lrow * GSH + lc8] = pw;
        }
        __syncthreads();
    }

    // Epilogue: bias + store
#pragma unroll
    for (int mt = 0; mt < 2; ++mt) {
#pragma unroll
        for (int nt = 0; nt < 8; ++nt) {
            int row = bm + wm * 32 + mt * 16 + r0;
            int col = bn + wn * 64 + nt * 8 + 2 * kq;
            float bb0 = bias[col], bb1 = bias[col + 1];
            float v0 = c[mt][nt][0] + bb0, v1 = c[mt][nt][1] + bb1;
            float v2 = c[mt][nt][2] + bb0, v3 = c[mt][nt][3] + bb1;
            if (HALF_OUT) {
                __half2* Ch = (__half2*)C;
                Ch[((size_t)row * DIM + col) >> 1]       = __floats2half2_rn(v0, v1);
                Ch[((size_t)(row + 8) * DIM + col) >> 1] = __floats2half2_rn(v2, v3);
            } else {
                float* Cf = (float*)C;
                *(float2*)&Cf[(size_t)row * DIM + col]       = make_float2(v0, v1);
                *(float2*)&Cf[(size_t)(row + 8) * DIM + col] = make_float2(v2, v3);
            }
        }
    }
}

// ---------------------------------------------------------------------------
// Fused RMSNorm+RoPE (y=0: q, y=1: k) AND V-transpose (y=2) in ONE launch.
// Shared buffers overlay in a 16-byte-aligned union.
// ---------------------------------------------------------------------------
struct __align__(16) NTShared {
    union {
        struct {
            float sh[DIM];
            float red[8];
            float s_r;
        } n;
        __half tile[64][80];
    } u;
};

__global__ __launch_bounds__(256) void norm_and_transpose_kernel(
    __half* __restrict__ Xq, __half* __restrict__ Xk,
    const float* __restrict__ gqv, const float* __restrict__ gkv)
{
    __shared__ NTShared S;

    const int t = threadIdx.x;

    if (blockIdx.y == 2) {
        // ---- V transpose: g_vh[s][h*128+d] -> g_vt[h][d][s] ----
        const int bx = blockIdx.x;
        if (bx >= (SEQ / 64) * 2 * NHEADS) return;
        const int sblk = bx % (SEQ / 64);
        const int hz   = bx / (SEQ / 64);       // 0..23
        const int h    = hz >> 1;
        const int d0   = (hz & 1) * 64;
        const int s0   = sblk * 64;

        for (int i = t; i < 512; i += 256) {
            int r = i >> 3, c8 = (i & 7) * 8;
            uint4 v = *(const uint4*)&g_vh[(size_t)(s0 + r) * DIM + h * HDIM + d0 + c8];
            *(uint4*)&S.u.tile[r][c8] = v;
        }
        __syncthreads();
        for (int i = t; i < 512; i += 256) {
            int r = i >> 3, c8 = (i & 7) * 8;
            __half tmp[8];
#pragma unroll
            for (int j = 0; j < 8; ++j) tmp[j] = S.u.tile[c8 + j][r];
            *(uint4*)&g_vt[(size_t)(h * HDIM + d0 + r) * SEQ + s0 + c8] = *(uint4*)tmp;
        }
        return;
    }

    // ---- RMSNorm + RoPE ----
    const int s = blockIdx.x;
    const int which = blockIdx.y;
    __half* X = which ? Xk : Xq;
    const float* g = which ? gkv : gqv;

    __half2* row = (__half2*)(X + (size_t)s * DIM);

    float ss = 0.f;
    for (int i = t; i < DIM / 2; i += 256) {
        float2 f = __half22float2(row[i]);
        S.u.n.sh[2 * i]     = f.x;
        S.u.n.sh[2 * i + 1] = f.y;
        ss += f.x * f.x + f.y * f.y;
    }
#pragma unroll
    for (int off = 16; off > 0; off >>= 1)
        ss += __shfl_xor_sync(0xFFFFFFFFu, ss, off);
    if ((t & 31) == 0) S.u.n.red[t >> 5] = ss;
    __syncthreads();
    if (t == 0) {
        float tot = 0.f;
#pragma unroll
        for (int w = 0; w < 8; w++) tot += S.u.n.red[w];
        S.u.n.s_r = rsqrtf(tot / (float)DIM + EPS);
    }
    __syncthreads();
    const float r = S.u.n.s_r;

    for (int p = t; p < DIM / 2; p += 256) {
        int j = p & 63;
        float c  = g_trig[((size_t)s * 64 + j) * 2 + 0];
        float sn = g_trig[((size_t)s * 64 + j) * 2 + 1];
        float v0 = S.u.n.sh[2 * p] * r * g[2 * p];
        float v1 = S.u.n.sh[2 * p + 1] * r * g[2 * p + 1];
        row[p] = __floats2half2_rn(v0 * c - v1 * sn, v0 * sn + v1 * c);
    }
}

// ---------------------------------------------------------------------------
// fp16 flash attention, cp.async double-buffered K/V + FA2 register P-fragments
// (C-fragment of QK^T == A-fragment of PV for m16n8k16; no smem round-trip).
// 128 threads (4 warps), BQ=64 (16 rows/warp), BK=64, 2 CTAs/SM.
// ---------------------------------------------------------------------------
#define KSH 136
#define VSH 72
// 2 K buffers + 2 V buffers (Ps eliminated)
#define FA_SMEM_BYTES ((2 * 64 * KSH + 2 * 128 * VSH) * 2)   // 71680

__global__ __launch_bounds__(128, 2) void flash_h_kernel(
    const __half* __restrict__ Q, const __half* __restrict__ Kg,
    const __half* __restrict__ Vt, __half* __restrict__ O)
{
    extern __shared__ __align__(16) __half smh[];
    __half* Kb[2];
    __half* Vb[2];
    Kb[0] = smh;
    Kb[1] = Kb[0] + 64 * KSH;
    Vb[0] = Kb[1] + 64 * KSH;
    Vb[1] = Vb[0] + 128 * VSH;

    const int h    = blockIdx.y;
    const int qb   = blockIdx.x;
    const int t    = threadIdx.x;
    const int lane = t & 31;
    const int warp = t >> 5;
    const int r0   = lane >> 2;
    const int qc   = lane & 3;
    const float scale = 0.08838834764831845f;   // 1/sqrt(128)

    // ---- Stage Q tile into Kb[0], pull A-fragments to registers ----
    {
        const __half* src = Q + (size_t)(qb * 64) * DIM + h * HDIM;
        for (int i = t; i < 64 * 16; i += 128) {
            int r = i >> 4, c8 = (i & 15) * 8;
            *(uint4*)&Kb[0][r * KSH + c8] = *(const uint4*)&src[(size_t)r * DIM + c8];
        }
    }
    __syncthreads();

    unsigned qa[8][4];
    {
        const int rb = warp * 16 + r0;
#pragma unroll
        for (int kt = 0; kt < 8; ++kt) {
            int kc = kt * 16 + 2 * qc;
            qa[kt][0] = ld32h(&Kb[0][rb * KSH + kc]);
            qa[kt][1] = ld32h(&Kb[0][(rb + 8) * KSH + kc]);
            qa[kt][2] = ld32h(&Kb[0][rb * KSH + kc + 8]);
            qa[kt][3] = ld32h(&Kb[0][(rb + 8) * KSH + kc + 8]);
        }
    }
    __syncthreads();

    // ---- cp.async stage: K/V tile kb into buffer kb&1 ----
    auto stage_kv = [&](int kb) {
        __half* dk = Kb[kb & 1];
        __half* dv = Vb[kb & 1];
        const __half* ksrc = Kg + (size_t)(kb * 64) * DIM + h * HDIM;
        const __half* vsrc = Vt + (size_t)h * HDIM * SEQ + kb * 64;
        for (int i = t; i < 64 * 16; i += 128) {
            int r = i >> 4, c8 = (i & 15) * 8;
            cp16(&dk[r * KSH + c8], &ksrc[(size_t)r * DIM + c8]);
        }
        for (int i = t; i < 128 * 8; i += 128) {
            int r = i >> 3, c8 = (i & 7) * 8;
            cp16(&dv[r * VSH + c8], &vsrc[(size_t)r * SEQ + c8]);
        }
        cp_commit();
    };

    stage_kv(0);
    stage_kv(1);

    float o[16][4];
#pragma unroll
    for (int nt = 0; nt < 16; ++nt)
#pragma unroll
        for (int j = 0; j < 4; ++j) o[nt][j] = 0.f;

    float m0 = -1e30f, m1 = -1e30f, l0 = 0.f, l1 = 0.f;
    const int NT = SEQ / 64;   // 64

    for (int kb = 0; kb < NT; ++kb) {
        if (kb + 1 < NT) cp_wait<1>(); else cp_wait<0>();
        __syncthreads();

        const __half* Ks = Kb[kb & 1];
        const __half* Vs = Vb[kb & 1];

        // ---- S = Q @ K^T (per warp: 16 x 64) ----
        float s[8][4];
#pragma unroll
        for (int nt = 0; nt < 8; ++nt)
#pragma unroll
            for (int j = 0; j < 4; ++j) s[nt][j] = 0.f;

#pragma unroll
        for (int nt = 0; nt < 8; ++nt) {
            const int nb = (nt * 8 + r0) * KSH + 2 * qc;
#pragma unroll
            for (int kt = 0; kt < 8; ++kt) {
                unsigned b0 = ld32h(&Ks[nb + kt * 16]);
                unsigned b1 = ld32h(&Ks[nb + kt * 16 + 8]);
                mma_f16(s[nt], qa[kt], b0, b1);
            }
        }

        // ---- Online softmax ----
        float mx0 = -1e30f, mx1 = -1e30f;
#pragma unroll
        for (int nt = 0; nt < 8; ++nt) {
            mx0 = fmaxf(mx0, fmaxf(s[nt][0], s[nt][1]));
            mx1 = fmaxf(mx1, fmaxf(s[nt][2], s[nt][3]));
        }
        mx0 = fmaxf(mx0, __shfl_xor_sync(0xFFFFFFFFu, mx0, 1));
        mx0 = fmaxf(mx0, __shfl_xor_sync(0xFFFFFFFFu, mx0, 2));
        mx1 = fmaxf(mx1, __shfl_xor_sync(0xFFFFFFFFu, mx1, 1));
        mx1 = fmaxf(mx1, __shfl_xor_sync(0xFFFFFFFFu, mx1, 2));

        float nm0 = fmaxf(m0, mx0 * scale);
        float nm1 = fmaxf(m1, mx1 * scale);
        float corr0 = __expf(m0 - nm0);
        float corr1 = __expf(m1 - nm1);

        float sum0 = 0.f, sum1 = 0.f;
#pragma unroll
        for (int nt = 0; nt < 8; ++nt) {
            s[nt][0] = __expf(s[nt][0] * scale - nm0);
            s[nt][1] = __expf(s[nt][1] * scale - nm0);
            s[nt][2] = __expf(s[nt][2] * scale - nm1);
            s[nt][3] = __expf(s[nt][3] * scale - nm1);
            sum0 += s[nt][0] + s[nt][1];
            sum1 += s[nt][2] + s[nt][3];
        }
        sum0 += __shfl_xor_sync(0xFFFFFFFFu, sum0, 1);
        sum0 += __shfl_xor_sync(0xFFFFFFFFu, sum0, 2);
        sum1 += __shfl_xor_sync(0xFFFFFFFFu, sum1, 1);
        sum1 += __shfl_xor_sync(0xFFFFFFFFu, sum1, 2);

        l0 = l0 * corr0 + sum0;
        l1 = l1 * corr1 + sum1;
        m0 = nm0;
        m1 = nm1;

#pragma unroll
        for (int nt = 0; nt < 16; ++nt) {
            o[nt][0] *= corr0; o[nt][1] *= corr0;
            o[nt][2] *= corr1; o[nt][3] *= corr1;
        }

        // ---- O += P @ V : P A-fragments built directly from S C-fragments ----
        // (m16n8k16: C-frag rows r0/r0+8 cols nt*8+2qc,+1 == A-frag k-slices)
#pragma unroll
        for (int kt = 0; kt < 4; ++kt) {
            unsigned a[4];
            a[0] = packh2(s[2 * kt][0],     s[2 * kt][1]);
            a[1] = packh2(s[2 * kt][2],     s[2 * kt][3]);
            a[2] = packh2(s[2 * kt + 1][0], s[2 * kt + 1][1]);
            a[3] = packh2(s[2 * kt + 1][2], s[2 * kt + 1][3]);
#pragma unroll
            for (int nt = 0; nt < 16; ++nt) {
                const int nb = (nt * 8 + r0) * VSH + kt * 16 + 2 * qc;
                unsigned b0 = ld32h(&Vs[nb]);
                unsigned b1 = ld32h(&Vs[nb + 8]);
                mma_f16(o[nt], a, b0, b1);
            }
        }

        __syncthreads();                 // all warps done reading buffer kb&1
        if (kb + 2 < NT) stage_kv(kb + 2);
    }

    // ---- Epilogue: normalize, fp16 store ----
    float inv0 = 1.f / l0, inv1 = 1.f / l1;
    int grow = qb * 64 + warp * 16 + r0;
#pragma unroll
    for (int nt = 0; nt < 16; ++nt) {
        int col = h * HDIM + nt * 8 + 2 * qc;
        *(__half2*)&O[(size_t)grow * DIM + col] =
            __floats2half2_rn(o[nt][0] * inv0, o[nt][1] * inv0);
        *(__half2*)&O[(size_t)(grow + 8) * DIM + col] =
            __floats2half2_rn(o[nt][2] * inv1, o[nt][3] * inv1);
    }
}

// ---------------------------------------------------------------------------
// Launch
// ---------------------------------------------------------------------------
extern "C" void kernel_launch(void* const* d_in, const int* in_sizes, int n_in,
                              void* d_out, int out_size)
{
    const float* x     = (const float*)d_in[0];
    const float* freqs = (const float*)d_in[1];
    const float* Wq    = (const float*)d_in[2];
    const float* bq    = (const float*)d_in[3];
    const float* Wk    = (const float*)d_in[4];
    const float* bk    = (const float*)d_in[5];
    const float* Wv    = (const float*)d_in[6];
    const float* bv    = (const float*)d_in[7];
    const float* Wo    = (const float*)d_in[8];
    const float* bo    = (const float*)d_in[9];
    const float* gq    = (const float*)d_in[10];
    const float* gk    = (const float*)d_in[11];
    float* out = (float*)d_out;

    __half *xh, *qh, *kh, *vh, *attnh, *wqh, *wkh, *wvh, *woh, *vt;
    cudaGetSymbolAddress((void**)&xh,    g_xh);
    cudaGetSymbolAddress((void**)&qh,    g_qh);
    cudaGetSymbolAddress((void**)&kh,    g_kh);
    cudaGetSymbolAddress((void**)&vh,    g_vh);
    cudaGetSymbolAddress((void**)&attnh, g_attnh);
    cudaGetSymbolAddress((void**)&wqh,   g_wqh);
    cudaGetSymbolAddress((void**)&wkh,   g_wkh);
    cudaGetSymbolAddress((void**)&wvh,   g_wvh);
    cudaGetSymbolAddress((void**)&woh,   g_woh);
    cudaGetSymbolAddress((void**)&vt,    g_vt);

    cudaFuncSetAttribute(flash_h_kernel,
                         cudaFuncAttributeMaxDynamicSharedMemorySize, FA_SMEM_BYTES);

    // Prep: trig + fp16 conversion (single fused launch).
    trig_kernel<<<(SEQ * 64 + 255) / 256, 256>>>(freqs);
    to_half_all_kernel<<<dim3(SEQ * DIM / 4 / 256, 5), 256>>>(x, Wq, Wk, Wv, Wo);

    // Fused Q/K/V projection (fp16 in/out).
    dim3 qkv_grid(DIM / 128, SEQ / 128, 3);
    gemm_h_kernel<1><<<qkv_grid, 256>>>(
        xh, wqh, wkh, wvh, bq, bk, bv, qh, kh, vh);

    // RMSNorm+RoPE (q,k) and V transpose in one launch.
    norm_and_transpose_kernel<<<dim3(SEQ, 3), 256>>>(qh, kh, gq, gk);

    // Flash attention: BQ=64, 4 warps, 2 CTAs/SM, cp.async + register P-frags.
    flash_h_kernel<<<dim3(SEQ / 64, NHEADS), 128, FA_SMEM_BYTES>>>(qh, kh, vt, attnh);

    // Output projection (fp32 out).
    dim3 o_grid(DIM / 128, SEQ / 128, 1);
    gemm_h_kernel<0><<<o_grid, 256>>>(
        attnh, woh, woh, woh, bo, bo, bo, out, out, out);
}

// round 14
// speedup vs baseline: 1.7013x; 1.1589x over previous
#include <cuda_runtime.h>
#include <cuda_fp16.h>
#include <math.h>
#include <stdint.h>

// ---------------------------------------------------------------------------
// Problem constants (B=1, S=4096, DIM=1536, HEADS=12, HEAD_DIM=128)
// ---------------------------------------------------------------------------
#define SEQ    4096
#define DIM    1536
#define NHEADS 12
#define HDIM   128
#define EPS    1e-6f

// Scratch (allocation-free rule: __device__ globals)
__device__ __half g_xh[SEQ * DIM];
__device__ __half g_qh[SEQ * DIM];
__device__ __half g_kh[SEQ * DIM];
__device__ __half g_vh[SEQ * DIM];
__device__ __half g_attnh[SEQ * DIM];
__device__ __half g_wqh[DIM * DIM];
__device__ __half g_wkh[DIM * DIM];
__device__ __half g_wvh[DIM * DIM];
__device__ __half g_woh[DIM * DIM];
__device__ __half g_vt[NHEADS * HDIM * SEQ];   // V transposed: [h][d][s]
__device__ float  g_trig[SEQ * 64 * 2];        // cos,sin per (pos, pair)

// ---------------------------------------------------------------------------
// Helpers
// ---------------------------------------------------------------------------
__device__ __forceinline__ unsigned ld32h(const __half* p) {
    return *(const unsigned*)p;
}

__device__ __forceinline__ unsigned packh2(float x, float y) {
    __half2 h = __floats2half2_rn(x, y);
    return *(unsigned*)&h;
}

// D += A*B, m16n8k16, fp16 inputs, f32 accumulate
__device__ __forceinline__ void mma_f16(float* d, const unsigned* a,
                                        unsigned b0, unsigned b1) {
    asm volatile(
        "mma.sync.aligned.m16n8k16.row.col.f32.f16.f16.f32 "
        "{%0,%1,%2,%3}, {%4,%5,%6,%7}, {%8,%9}, {%0,%1,%2,%3};\n"
        : "+f"(d[0]), "+f"(d[1]), "+f"(d[2]), "+f"(d[3])
        : "r"(a[0]), "r"(a[1]), "r"(a[2]), "r"(a[3]), "r"(b0), "r"(b1));
}

// ldmatrix x4: four 8x8 fp16 tiles, one per output register.
__device__ __forceinline__ void ldsm_x4(unsigned& r0, unsigned& r1,
                                        unsigned& r2, unsigned& r3,
                                        const __half* p) {
    unsigned addr = (unsigned)__cvta_generic_to_shared(p);
    asm volatile(
        "ldmatrix.sync.aligned.m8n8.x4.shared.b16 {%0,%1,%2,%3}, [%4];"
        : "=r"(r0), "=r"(r1), "=r"(r2), "=r"(r3) : "r"(addr));
}

__device__ __forceinline__ void cp16(void* smem_dst, const void* gsrc) {
    unsigned s = (unsigned)__cvta_generic_to_shared(smem_dst);
    asm volatile("cp.async.cg.shared.global [%0], [%1], 16;\n" :: "r"(s), "l"(gsrc));
}
__device__ __forceinline__ void cp_commit() {
    asm volatile("cp.async.commit_group;\n");
}
template <int N>
__device__ __forceinline__ void cp_wait() {
    asm volatile("cp.async.wait_group %0;\n" :: "n"(N));
}

// ---------------------------------------------------------------------------
// Prep: fp32 -> fp16, 5 segments in one launch (y: 0=x, 1..4=Wq,Wk,Wv,Wo)
// ---------------------------------------------------------------------------
__global__ __launch_bounds__(256) void to_half_all_kernel(
    const float* __restrict__ x,  const float* __restrict__ Wq,
    const float* __restrict__ Wk, const float* __restrict__ Wv,
    const float* __restrict__ Wo)
{
    const int seg = blockIdx.y;
    const float* src;
    __half* dst;
    int n4;
    if (seg == 0)      { src = x;  dst = g_xh;  n4 = SEQ * DIM / 4; }
    else if (seg == 1) { src = Wq; dst = g_wqh; n4 = DIM * DIM / 4; }
    else if (seg == 2) { src = Wk; dst = g_wkh; n4 = DIM * DIM / 4; }
    else if (seg == 3) { src = Wv; dst = g_wvh; n4 = DIM * DIM / 4; }
    else               { src = Wo; dst = g_woh; n4 = DIM * DIM / 4; }

    int i = blockIdx.x * blockDim.x + threadIdx.x;
    if (i >= n4) return;
    float4 v = ((const float4*)src)[i];
    __half2* d = (__half2*)dst;
    d[2 * i + 0] = __floats2half2_rn(v.x, v.y);
    d[2 * i + 1] = __floats2half2_rn(v.z, v.w);
}

// ---------------------------------------------------------------------------
// RoPE trig table with double-precision range reduction.
// ---------------------------------------------------------------------------
__global__ __launch_bounds__(256) void trig_kernel(const float* __restrict__ freqs) {
    int idx = blockIdx.x * blockDim.x + threadIdx.x;
    if (idx >= SEQ * 64) return;
    double a = (double)freqs[idx];
    double s, c;
    sincos(a, &s, &c);
    g_trig[idx * 2 + 0] = (float)c;
    g_trig[idx * 2 + 1] = (float)s;
}

// ---------------------------------------------------------------------------
// fp16 tensor-core GEMM, multi-output over blockIdx.z (R7 structure):
//   C_z[M,N] = A[M,K] @ W_z[N,K]^T + bias_z[N]
// BM=BN=128, BK=16, 256 threads (8 warps 4m x 2n), warp tile 32x64.
// Register-prefetch double buffer; smem stride 24 halfs (bank-conflict-free).
// ---------------------------------------------------------------------------
#define GSH 24

template <int HALF_OUT>
__global__ __launch_bounds__(256, 2) void gemm_h_kernel(
    const __half* __restrict__ A,
    const __half* __restrict__ W0, const __half* __restrict__ W1,
    const __half* __restrict__ W2,
    const float* __restrict__ b0p, const float* __restrict__ b1p,
    const float* __restrict__ b2p,
    void* C0, void* C1, void* C2)
{
    __shared__ __align__(16) __half As[2][128 * GSH];
    __shared__ __align__(16) __half Ws[2][128 * GSH];

    const int z = blockIdx.z;
    const __half* W   = (z == 0) ? W0  : (z == 1) ? W1  : W2;
    const float* bias = (z == 0) ? b0p : (z == 1) ? b1p : b2p;
    void* C           = (z == 0) ? C0  : (z == 1) ? C1  : C2;

    const int t    = threadIdx.x;
    const int lane = t & 31;
    const int warp = t >> 5;
    const int wm   = warp >> 1;     // 0..3
    const int wn   = warp & 1;      // 0..1
    const int bm   = blockIdx.y * 128;
    const int bn   = blockIdx.x * 128;

    const int lrow = t >> 1;            // 0..127
    const int lc8  = (t & 1) * 8;       // 0 or 8

    const __half* Ap = A + (size_t)(bm + lrow) * DIM + lc8;
    const __half* Wp = W + (size_t)(bn + lrow) * DIM + lc8;

    float c[2][8][4];
#pragma unroll
    for (int mt = 0; mt < 2; mt++)
#pragma unroll
        for (int nt = 0; nt < 8; nt++)
#pragma unroll
            for (int j = 0; j < 4; j++) c[mt][nt][j] = 0.f;

    const int KITERS = DIM / 16;   // 96

    uint4 pa = *(const uint4*)Ap;
    uint4 pw = *(const uint4*)Wp;
    *(uint4*)&As[0][lrow * GSH + lc8] = pa;
    *(uint4*)&Ws[0][lrow * GSH + lc8] = pw;
    __syncthreads();

    const int r0  = lane >> 2;
    const int kq  = lane & 3;
    const int r_a = wm * 32 + r0;
    const int r_b = wn * 64 + r0;

    for (int it = 0; it < KITERS; ++it) {
        const int cur = it & 1;
        if (it + 1 < KITERS) {
            pa = *(const uint4*)(Ap + (it + 1) * 16);
            pw = *(const uint4*)(Wp + (it + 1) * 16);
        }

        const __half* as = As[cur];
        const __half* ws = Ws[cur];

        unsigned a[2][4];
#pragma unroll
        for (int mt = 0; mt < 2; ++mt) {
            int r = r_a + mt * 16;
            a[mt][0] = ld32h(&as[r * GSH + 2 * kq]);
            a[mt][1] = ld32h(&as[(r + 8) * GSH + 2 * kq]);
            a[mt][2] = ld32h(&as[r * GSH + 2 * kq + 8]);
            a[mt][3] = ld32h(&as[(r + 8) * GSH + 2 * kq + 8]);
        }
#pragma unroll
        for (int nt = 0; nt < 8; ++nt) {
            int n = r_b + nt * 8;
            unsigned bb0 = ld32h(&ws[n * GSH + 2 * kq]);
            unsigned bb1 = ld32h(&ws[n * GSH + 2 * kq + 8]);
            mma_f16(c[0][nt], a[0], bb0, bb1);
            mma_f16(c[1][nt], a[1], bb0, bb1);
        }

        if (it + 1 < KITERS) {
            *(uint4*)&As[cur ^ 1][lrow * GSH + lc8] = pa;
            *(uint4*)&Ws[cur ^ 1][lrow * GSH + lc8] = pw;
        }
        __syncthreads();
    }

    // Epilogue: bias + store
#pragma unroll
    for (int mt = 0; mt < 2; ++mt) {
#pragma unroll
        for (int nt = 0; nt < 8; ++nt) {
            int row = bm + wm * 32 + mt * 16 + r0;
            int col = bn + wn * 64 + nt * 8 + 2 * kq;
            float bb0 = bias[col], bb1 = bias[col + 1];
            float v0 = c[mt][nt][0] + bb0, v1 = c[mt][nt][1] + bb1;
            float v2 = c[mt][nt][2] + bb0, v3 = c[mt][nt][3] + bb1;
            if (HALF_OUT) {
                __half2* Ch = (__half2*)C;
                Ch[((size_t)row * DIM + col) >> 1]       = __floats2half2_rn(v0, v1);
                Ch[((size_t)(row + 8) * DIM + col) >> 1] = __floats2half2_rn(v2, v3);
            } else {
                float* Cf = (float*)C;
                *(float2*)&Cf[(size_t)row * DIM + col]       = make_float2(v0, v1);
                *(float2*)&Cf[(size_t)(row + 8) * DIM + col] = make_float2(v2, v3);
            }
        }
    }
}

// ---------------------------------------------------------------------------
// Fused RMSNorm+RoPE (y=0: q, y=1: k) AND V-transpose (y=2) in ONE launch.
// Shared buffers overlay in a 16-byte-aligned union.
// ---------------------------------------------------------------------------
struct __align__(16) NTShared {
    union {
        struct {
            float sh[DIM];
            float red[8];
            float s_r;
        } n;
        __half tile[64][80];
    } u;
};

__global__ __launch_bounds__(256) void norm_and_transpose_kernel(
    __half* __restrict__ Xq, __half* __restrict__ Xk,
    const float* __restrict__ gqv, const float* __restrict__ gkv)
{
    __shared__ NTShared S;

    const int t = threadIdx.x;

    if (blockIdx.y == 2) {
        // ---- V transpose: g_vh[s][h*128+d] -> g_vt[h][d][s] ----
        const int bx = blockIdx.x;
        if (bx >= (SEQ / 64) * 2 * NHEADS) return;
        const int sblk = bx % (SEQ / 64);
        const int hz   = bx / (SEQ / 64);       // 0..23
        const int h    = hz >> 1;
        const int d0   = (hz & 1) * 64;
        const int s0   = sblk * 64;

        for (int i = t; i < 512; i += 256) {
            int r = i >> 3, c8 = (i & 7) * 8;
            uint4 v = *(const uint4*)&g_vh[(size_t)(s0 + r) * DIM + h * HDIM + d0 + c8];
            *(uint4*)&S.u.tile[r][c8] = v;
        }
        __syncthreads();
        for (int i = t; i < 512; i += 256) {
            int r = i >> 3, c8 = (i & 7) * 8;
            __half tmp[8];
#pragma unroll
            for (int j = 0; j < 8; ++j) tmp[j] = S.u.tile[c8 + j][r];
            *(uint4*)&g_vt[(size_t)(h * HDIM + d0 + r) * SEQ + s0 + c8] = *(uint4*)tmp;
        }
        return;
    }

    // ---- RMSNorm + RoPE ----
    const int s = blockIdx.x;
    const int which = blockIdx.y;
    __half* X = which ? Xk : Xq;
    const float* g = which ? gkv : gqv;

    __half2* row = (__half2*)(X + (size_t)s * DIM);

    float ss = 0.f;
    for (int i = t; i < DIM / 2; i += 256) {
        float2 f = __half22float2(row[i]);
        S.u.n.sh[2 * i]     = f.x;
        S.u.n.sh[2 * i + 1] = f.y;
        ss += f.x * f.x + f.y * f.y;
    }
#pragma unroll
    for (int off = 16; off > 0; off >>= 1)
        ss += __shfl_xor_sync(0xFFFFFFFFu, ss, off);
    if ((t & 31) == 0) S.u.n.red[t >> 5] = ss;
    __syncthreads();
    if (t == 0) {
        float tot = 0.f;
#pragma unroll
        for (int w = 0; w < 8; w++) tot += S.u.n.red[w];
        S.u.n.s_r = rsqrtf(tot / (float)DIM + EPS);
    }
    __syncthreads();
    const float r = S.u.n.s_r;

    for (int p = t; p < DIM / 2; p += 256) {
        int j = p & 63;
        float c  = g_trig[((size_t)s * 64 + j) * 2 + 0];
        float sn = g_trig[((size_t)s * 64 + j) * 2 + 1];
        float v0 = S.u.n.sh[2 * p] * r * g[2 * p];
        float v1 = S.u.n.sh[2 * p + 1] * r * g[2 * p + 1];
        row[p] = __floats2half2_rn(v0 * c - v1 * sn, v0 * sn + v1 * c);
    }
}

// ---------------------------------------------------------------------------
// fp16 flash attention: cp.async double-buffered K/V + FA2 register P-frags
// + ldmatrix.x4 B-operand loads (4 frag regs / instruction).
// 128 threads (4 warps), BQ=64 (16 rows/warp), BK=64, 2 CTAs/SM.
// ---------------------------------------------------------------------------
#define KSH 136
#define VSH 72
// 2 K buffers + 2 V buffers
#define FA_SMEM_BYTES ((2 * 64 * KSH + 2 * 128 * VSH) * 2)   // 71680

__global__ __launch_bounds__(128, 2) void flash_h_kernel(
    const __half* __restrict__ Q, const __half* __restrict__ Kg,
    const __half* __restrict__ Vt, __half* __restrict__ O)
{
    extern __shared__ __align__(16) __half smh[];
    __half* Kb[2];
    __half* Vb[2];
    Kb[0] = smh;
    Kb[1] = Kb[0] + 64 * KSH;
    Vb[0] = Kb[1] + 64 * KSH;
    Vb[1] = Vb[0] + 128 * VSH;

    const int h    = blockIdx.y;
    const int qb   = blockIdx.x;
    const int t    = threadIdx.x;
    const int lane = t & 31;
    const int warp = t >> 5;
    const int r0   = lane >> 2;
    const int qc   = lane & 3;
    const float scale = 0.08838834764831845f;   // 1/sqrt(128)

    // ldmatrix per-lane address components.
    const int lrow = lane & 7;          // row within 8x8 tile
    const int ltile = lane >> 3;        // which tile (0..3)
    // S-loop (K): tiles = (kt-pair): t0: k+0, t1: k+8, t2: k+16, t3: k+24
    const int offK = lrow * KSH + (ltile >> 1) * 16 + (ltile & 1) * 8;
    // PV (Vt): tiles = (nt-pair): t0: n+0,k+0  t1: n+0,k+8  t2: n+8,k+0  t3: n+8,k+8
    const int offV = ((ltile >> 1) * 8 + lrow) * VSH + (ltile & 1) * 8;

    // ---- Stage Q tile into Kb[0], pull A-fragments to registers ----
    {
        const __half* src = Q + (size_t)(qb * 64) * DIM + h * HDIM;
        for (int i = t; i < 64 * 16; i += 128) {
            int r = i >> 4, c8 = (i & 15) * 8;
            *(uint4*)&Kb[0][r * KSH + c8] = *(const uint4*)&src[(size_t)r * DIM + c8];
        }
    }
    __syncthreads();

    unsigned qa[8][4];
    {
        const int rb = warp * 16 + r0;
#pragma unroll
        for (int kt = 0; kt < 8; ++kt) {
            int kc = kt * 16 + 2 * qc;
            qa[kt][0] = ld32h(&Kb[0][rb * KSH + kc]);
            qa[kt][1] = ld32h(&Kb[0][(rb + 8) * KSH + kc]);
            qa[kt][2] = ld32h(&Kb[0][rb * KSH + kc + 8]);
            qa[kt][3] = ld32h(&Kb[0][(rb + 8) * KSH + kc + 8]);
        }
    }
    __syncthreads();

    // ---- cp.async stage: K/V tile kb into buffer kb&1 ----
    auto stage_kv = [&](int kb) {
        __half* dk = Kb[kb & 1];
        __half* dv = Vb[kb & 1];
        const __half* ksrc = Kg + (size_t)(kb * 64) * DIM + h * HDIM;
        const __half* vsrc = Vt + (size_t)h * HDIM * SEQ + kb * 64;
        for (int i = t; i < 64 * 16; i += 128) {
            int r = i >> 4, c8 = (i & 15) * 8;
            cp16(&dk[r * KSH + c8], &ksrc[(size_t)r * DIM + c8]);
        }
        for (int i = t; i < 128 * 8; i += 128) {
            int r = i >> 3, c8 = (i & 7) * 8;
            cp16(&dv[r * VSH + c8], &vsrc[(size_t)r * SEQ + c8]);
        }
        cp_commit();
    };

    stage_kv(0);
    stage_kv(1);

    float o[16][4];
#pragma unroll
    for (int nt = 0; nt < 16; ++nt)
#pragma unroll
        for (int j = 0; j < 4; ++j) o[nt][j] = 0.f;

    float m0 = -1e30f, m1 = -1e30f, l0 = 0.f, l1 = 0.f;
    const int NT = SEQ / 64;   // 64

    for (int kb = 0; kb < NT; ++kb) {
        if (kb + 1 < NT) cp_wait<1>(); else cp_wait<0>();
        __syncthreads();

        const __half* Ks = Kb[kb & 1];
        const __half* Vs = Vb[kb & 1];

        // ---- S = Q @ K^T (per warp: 16 x 64); B via ldmatrix.x4 ----
        float s[8][4];
#pragma unroll
        for (int nt = 0; nt < 8; ++nt)
#pragma unroll
            for (int j = 0; j < 4; ++j) s[nt][j] = 0.f;

#pragma unroll
        for (int nt = 0; nt < 8; ++nt) {
            const __half* kbase = Ks + nt * 8 * KSH + offK;
#pragma unroll
            for (int kt2 = 0; kt2 < 4; ++kt2) {
                unsigned b0, b1, b2, b3;
                ldsm_x4(b0, b1, b2, b3, kbase + kt2 * 32);
                mma_f16(s[nt], qa[2 * kt2],     b0, b1);
                mma_f16(s[nt], qa[2 * kt2 + 1], b2, b3);
            }
        }

        // ---- Online softmax ----
        float mx0 = -1e30f, mx1 = -1e30f;
#pragma unroll
        for (int nt = 0; nt < 8; ++nt) {
            mx0 = fmaxf(mx0, fmaxf(s[nt][0], s[nt][1]));
            mx1 = fmaxf(mx1, fmaxf(s[nt][2], s[nt][3]));
        }
        mx0 = fmaxf(mx0, __shfl_xor_sync(0xFFFFFFFFu, mx0, 1));
        mx0 = fmaxf(mx0, __shfl_xor_sync(0xFFFFFFFFu, mx0, 2));
        mx1 = fmaxf(mx1, __shfl_xor_sync(0xFFFFFFFFu, mx1, 1));
        mx1 = fmaxf(mx1, __shfl_xor_sync(0xFFFFFFFFu, mx1, 2));

        float nm0 = fmaxf(m0, mx0 * scale);
        float nm1 = fmaxf(m1, mx1 * scale);
        float corr0 = __expf(m0 - nm0);
        float corr1 = __expf(m1 - nm1);

        float sum0 = 0.f, sum1 = 0.f;
#pragma unroll
        for (int nt = 0; nt < 8; ++nt) {
            s[nt][0] = __expf(s[nt][0] * scale - nm0);
            s[nt][1] = __expf(s[nt][1] * scale - nm0);
            s[nt][2] = __expf(s[nt][2] * scale - nm1);
            s[nt][3] = __expf(s[nt][3] * scale - nm1);
            sum0 += s[nt][0] + s[nt][1];
            sum1 += s[nt][2] + s[nt][3];
        }
        sum0 += __shfl_xor_sync(0xFFFFFFFFu, sum0, 1);
        sum0 += __shfl_xor_sync(0xFFFFFFFFu, sum0, 2);
        sum1 += __shfl_xor_sync(0xFFFFFFFFu, sum1, 1);
        sum1 += __shfl_xor_sync(0xFFFFFFFFu, sum1, 2);

        l0 = l0 * corr0 + sum0;
        l1 = l1 * corr1 + sum1;
        m0 = nm0;
        m1 = nm1;

#pragma unroll
        for (int nt = 0; nt < 16; ++nt) {
            o[nt][0] *= corr0; o[nt][1] *= corr0;
            o[nt][2] *= corr1; o[nt][3] *= corr1;
        }

        // ---- O += P @ V : P A-frags from S C-frags; V B via ldmatrix.x4 ----
#pragma unroll
        for (int kt = 0; kt < 4; ++kt) {
            unsigned a[4];
            a[0] = packh2(s[2 * kt][0],     s[2 * kt][1]);
            a[1] = packh2(s[2 * kt][2],     s[2 * kt][3]);
            a[2] = packh2(s[2 * kt + 1][0], s[2 * kt + 1][1]);
            a[3] = packh2(s[2 * kt + 1][2], s[2 * kt + 1][3]);
            const __half* vbase = Vs + kt * 16 + offV;
#pragma unroll
            for (int nt2 = 0; nt2 < 8; ++nt2) {
                unsigned b0, b1, b2, b3;
                ldsm_x4(b0, b1, b2, b3, vbase + nt2 * 16 * VSH);
                mma_f16(o[2 * nt2],     a, b0, b1);
                mma_f16(o[2 * nt2 + 1], a, b2, b3);
            }
        }

        __syncthreads();                 // all warps done reading buffer kb&1
        if (kb + 2 < NT) stage_kv(kb + 2);
    }

    // ---- Epilogue: normalize, fp16 store ----
    float inv0 = 1.f / l0, inv1 = 1.f / l1;
    int grow = qb * 64 + warp * 16 + r0;
#pragma unroll
    for (int nt = 0; nt < 16; ++nt) {
        int col = h * HDIM + nt * 8 + 2 * qc;
        *(__half2*)&O[(size_t)grow * DIM + col] =
            __floats2half2_rn(o[nt][0] * inv0, o[nt][1] * inv0);
        *(__half2*)&O[(size_t)(grow + 8) * DIM + col] =
            __floats2half2_rn(o[nt][2] * inv1, o[nt][3] * inv1);
    }
}

// ---------------------------------------------------------------------------
// Launch
// ---------------------------------------------------------------------------
extern "C" void kernel_launch(void* const* d_in, const int* in_sizes, int n_in,
                              void* d_out, int out_size)
{
    const float* x     = (const float*)d_in[0];
    const float* freqs = (const float*)d_in[1];
    const float* Wq    = (const float*)d_in[2];
    const float* bq    = (const float*)d_in[3];
    const float* Wk    = (const float*)d_in[4];
    const float* bk    = (const float*)d_in[5];
    const float* Wv    = (const float*)d_in[6];
    const float* bv    = (const float*)d_in[7];
    const float* Wo    = (const float*)d_in[8];
    const float* bo    = (const float*)d_in[9];
    const float* gq    = (const float*)d_in[10];
    const float* gk    = (const float*)d_in[11];
    float* out = (float*)d_out;

    __half *xh, *qh, *kh, *vh, *attnh, *wqh, *wkh, *wvh, *woh, *vt;
    cudaGetSymbolAddress((void**)&xh,    g_xh);
    cudaGetSymbolAddress((void**)&qh,    g_qh);
    cudaGetSymbolAddress((void**)&kh,    g_kh);
    cudaGetSymbolAddress((void**)&vh,    g_vh);
    cudaGetSymbolAddress((void**)&attnh, g_attnh);
    cudaGetSymbolAddress((void**)&wqh,   g_wqh);
    cudaGetSymbolAddress((void**)&wkh,   g_wkh);
    cudaGetSymbolAddress((void**)&wvh,   g_wvh);
    cudaGetSymbolAddress((void**)&woh,   g_woh);
    cudaGetSymbolAddress((void**)&vt,    g_vt);

    cudaFuncSetAttribute(flash_h_kernel,
                         cudaFuncAttributeMaxDynamicSharedMemorySize, FA_SMEM_BYTES);

    // Prep: trig + fp16 conversion (single fused launch).
    trig_kernel<<<(SEQ * 64 + 255) / 256, 256>>>(freqs);
    to_half_all_kernel<<<dim3(SEQ * DIM / 4 / 256, 5), 256>>>(x, Wq, Wk, Wv, Wo);

    // Fused Q/K/V projection (fp16 in/out).
    dim3 qkv_grid(DIM / 128, SEQ / 128, 3);
    gemm_h_kernel<1><<<qkv_grid, 256>>>(
        xh, wqh, wkh, wvh, bq, bk, bv, qh, kh, vh);

    // RMSNorm+RoPE (q,k) and V transpose in one launch.
    norm_and_transpose_kernel<<<dim3(SEQ, 3), 256>>>(qh, kh, gq, gk);

    // Flash attention: cp.async + register P-frags + ldmatrix.
    flash_h_kernel<<<dim3(SEQ / 64, NHEADS), 128, FA_SMEM_BYTES>>>(qh, kh, vt, attnh);

    // Output projection (fp32 out).
    dim3 o_grid(DIM / 128, SEQ / 128, 1);
    gemm_h_kernel<0><<<o_grid, 256>>>(
        attnh, woh, woh, woh, bo, bo, bo, out, out, out);
}

// round 15
// speedup vs baseline: 1.7858x; 1.0497x over previous
#include <cuda_runtime.h>
#include <cuda_fp16.h>
#include <math.h>
#include <stdint.h>

// ---------------------------------------------------------------------------
// Problem constants (B=1, S=4096, DIM=1536, HEADS=12, HEAD_DIM=128)
// ---------------------------------------------------------------------------
#define SEQ    4096
#define DIM    1536
#define NHEADS 12
#define HDIM   128
#define EPS    1e-6f

// Scratch (allocation-free rule: __device__ globals)
__device__ __half g_xh[SEQ * DIM];
__device__ __half g_qh[SEQ * DIM];
__device__ __half g_kh[SEQ * DIM];
__device__ __half g_vh[SEQ * DIM];
__device__ __half g_attnh[SEQ * DIM];
__device__ __half g_wqh[DIM * DIM];
__device__ __half g_wkh[DIM * DIM];
__device__ __half g_wvh[DIM * DIM];
__device__ __half g_woh[DIM * DIM];
__device__ __half g_vt[NHEADS * HDIM * SEQ];   // V transposed: [h][d][s]
__device__ float  g_trig[SEQ * 64 * 2];        // cos,sin per (pos, pair)

// ---------------------------------------------------------------------------
// Helpers
// ---------------------------------------------------------------------------
__device__ __forceinline__ unsigned ld32h(const __half* p) {
    return *(const unsigned*)p;
}

__device__ __forceinline__ unsigned packh2(float x, float y) {
    __half2 h = __floats2half2_rn(x, y);
    return *(unsigned*)&h;
}

// D += A*B, m16n8k16, fp16 inputs, f32 accumulate
__device__ __forceinline__ void mma_f16(float* d, const unsigned* a,
                                        unsigned b0, unsigned b1) {
    asm volatile(
        "mma.sync.aligned.m16n8k16.row.col.f32.f16.f16.f32 "
        "{%0,%1,%2,%3}, {%4,%5,%6,%7}, {%8,%9}, {%0,%1,%2,%3};\n"
        : "+f"(d[0]), "+f"(d[1]), "+f"(d[2]), "+f"(d[3])
        : "r"(a[0]), "r"(a[1]), "r"(a[2]), "r"(a[3]), "r"(b0), "r"(b1));
}

// ldmatrix x4: four 8x8 fp16 tiles, one per output register.
__device__ __forceinline__ void ldsm_x4(unsigned& r0, unsigned& r1,
                                        unsigned& r2, unsigned& r3,
                                        const __half* p) {
    unsigned addr = (unsigned)__cvta_generic_to_shared(p);
    asm volatile(
        "ldmatrix.sync.aligned.m8n8.x4.shared.b16 {%0,%1,%2,%3}, [%4];"
        : "=r"(r0), "=r"(r1), "=r"(r2), "=r"(r3) : "r"(addr));
}

__device__ __forceinline__ void cp16(void* smem_dst, const void* gsrc) {
    unsigned s = (unsigned)__cvta_generic_to_shared(smem_dst);
    asm volatile("cp.async.cg.shared.global [%0], [%1], 16;\n" :: "r"(s), "l"(gsrc));
}
__device__ __forceinline__ void cp_commit() {
    asm volatile("cp.async.commit_group;\n");
}
template <int N>
__device__ __forceinline__ void cp_wait() {
    asm volatile("cp.async.wait_group %0;\n" :: "n"(N));
}

// ---------------------------------------------------------------------------
// Prep: fp32 -> fp16, 5 segments in one launch (y: 0=x, 1..4=Wq,Wk,Wv,Wo)
// ---------------------------------------------------------------------------
__global__ __launch_bounds__(256) void to_half_all_kernel(
    const float* __restrict__ x,  const float* __restrict__ Wq,
    const float* __restrict__ Wk, const float* __restrict__ Wv,
    const float* __restrict__ Wo)
{
    const int seg = blockIdx.y;
    const float* src;
    __half* dst;
    int n4;
    if (seg == 0)      { src = x;  dst = g_xh;  n4 = SEQ * DIM / 4; }
    else if (seg == 1) { src = Wq; dst = g_wqh; n4 = DIM * DIM / 4; }
    else if (seg == 2) { src = Wk; dst = g_wkh; n4 = DIM * DIM / 4; }
    else if (seg == 3) { src = Wv; dst = g_wvh; n4 = DIM * DIM / 4; }
    else               { src = Wo; dst = g_woh; n4 = DIM * DIM / 4; }

    int i = blockIdx.x * blockDim.x + threadIdx.x;
    if (i >= n4) return;
    float4 v = ((const float4*)src)[i];
    __half2* d = (__half2*)dst;
    d[2 * i + 0] = __floats2half2_rn(v.x, v.y);
    d[2 * i + 1] = __floats2half2_rn(v.z, v.w);
}

// ---------------------------------------------------------------------------
// RoPE trig table with double-precision range reduction.
// ---------------------------------------------------------------------------
__global__ __launch_bounds__(256) void trig_kernel(const float* __restrict__ freqs) {
    int idx = blockIdx.x * blockDim.x + threadIdx.x;
    if (idx >= SEQ * 64) return;
    double a = (double)freqs[idx];
    double s, c;
    sincos(a, &s, &c);
    g_trig[idx * 2 + 0] = (float)c;
    g_trig[idx * 2 + 1] = (float)s;
}

// ---------------------------------------------------------------------------
// fp16 tensor-core GEMM with ldmatrix.x4 operand loads:
//   C_z[M,N] = A[M,K] @ W_z[N,K]^T + bias_z[N]  (z = blockIdx.z)
// BM=BN=128, BK=16, 256 threads (8 warps 4m x 2n), warp tile 32x64.
// Register-prefetch double buffer; smem stride 24 halfs (48B: 3r mod 8
// permutation => ldmatrix conflict-free).
// ---------------------------------------------------------------------------
#define GSH 24

template <int HALF_OUT>
__global__ __launch_bounds__(256, 2) void gemm_h_kernel(
    const __half* __restrict__ A,
    const __half* __restrict__ W0, const __half* __restrict__ W1,
    const __half* __restrict__ W2,
    const float* __restrict__ b0p, const float* __restrict__ b1p,
    const float* __restrict__ b2p,
    void* C0, void* C1, void* C2)
{
    __shared__ __align__(16) __half As[2][128 * GSH];
    __shared__ __align__(16) __half Ws[2][128 * GSH];

    const int z = blockIdx.z;
    const __half* W   = (z == 0) ? W0  : (z == 1) ? W1  : W2;
    const float* bias = (z == 0) ? b0p : (z == 1) ? b1p : b2p;
    void* C           = (z == 0) ? C0  : (z == 1) ? C1  : C2;

    const int t    = threadIdx.x;
    const int lane = t & 31;
    const int warp = t >> 5;
    const int wm   = warp >> 1;     // 0..3
    const int wn   = warp & 1;      // 0..1
    const int bm   = blockIdx.y * 128;
    const int bn   = blockIdx.x * 128;

    const int lrow = t >> 1;            // 0..127
    const int lc8  = (t & 1) * 8;       // 0 or 8

    const __half* Ap = A + (size_t)(bm + lrow) * DIM + lc8;
    const __half* Wp = W + (size_t)(bn + lrow) * DIM + lc8;

    float c[2][8][4];
#pragma unroll
    for (int mt = 0; mt < 2; mt++)
#pragma unroll
        for (int nt = 0; nt < 8; nt++)
#pragma unroll
            for (int j = 0; j < 4; j++) c[mt][nt][j] = 0.f;

    const int KITERS = DIM / 16;   // 96

    uint4 pa = *(const uint4*)Ap;
    uint4 pw = *(const uint4*)Wp;
    *(uint4*)&As[0][lrow * GSH + lc8] = pa;
    *(uint4*)&Ws[0][lrow * GSH + lc8] = pw;
    __syncthreads();

    const int r0  = lane >> 2;
    const int kq  = lane & 3;

    // ldmatrix lane-address components.
    const int tl  = lane & 7;           // row within 8x8 tile
    const int ti  = lane >> 3;          // tile index 0..3
    // A tiles: t0=(rows+0,k0-8) t1=(rows+8,k0-8) t2=(rows+0,k8-16) t3=(rows+8,k8-16)
    const int offA = ((ti & 1) * 8 + tl) * GSH + (ti >> 1) * 8;
    // B tiles: t0=(n+0,k0-8) t1=(n+0,k8-16) t2=(n+8,k0-8) t3=(n+8,k8-16)
    const int offB = ((ti >> 1) * 8 + tl) * GSH + (ti & 1) * 8;

    const int r_a = wm * 32;            // warp A row base
    const int r_b = wn * 64;            // warp B row base

    for (int it = 0; it < KITERS; ++it) {
        const int cur = it & 1;
        if (it + 1 < KITERS) {
            pa = *(const uint4*)(Ap + (it + 1) * 16);
            pw = *(const uint4*)(Wp + (it + 1) * 16);
        }

        const __half* as = As[cur];
        const __half* ws = Ws[cur];

        unsigned a[2][4];
#pragma unroll
        for (int mt = 0; mt < 2; ++mt)
            ldsm_x4(a[mt][0], a[mt][1], a[mt][2], a[mt][3],
                    as + (r_a + mt * 16) * GSH + offA);

#pragma unroll
        for (int nt2 = 0; nt2 < 4; ++nt2) {
            unsigned b0, b1, b2, b3;
            ldsm_x4(b0, b1, b2, b3, ws + (r_b + nt2 * 16) * GSH + offB);
            mma_f16(c[0][2 * nt2],     a[0], b0, b1);
            mma_f16(c[1][2 * nt2],     a[1], b0, b1);
            mma_f16(c[0][2 * nt2 + 1], a[0], b2, b3);
            mma_f16(c[1][2 * nt2 + 1], a[1], b2, b3);
        }

        if (it + 1 < KITERS) {
            *(uint4*)&As[cur ^ 1][lrow * GSH + lc8] = pa;
            *(uint4*)&Ws[cur ^ 1][lrow * GSH + lc8] = pw;
        }
        __syncthreads();
    }

    // Epilogue: bias + store
#pragma unroll
    for (int mt = 0; mt < 2; ++mt) {
#pragma unroll
        for (int nt = 0; nt < 8; ++nt) {
            int row = bm + wm * 32 + mt * 16 + r0;
            int col = bn + wn * 64 + nt * 8 + 2 * kq;
            float bb0 = bias[col], bb1 = bias[col + 1];
            float v0 = c[mt][nt][0] + bb0, v1 = c[mt][nt][1] + bb1;
            float v2 = c[mt][nt][2] + bb0, v3 = c[mt][nt][3] + bb1;
            if (HALF_OUT) {
                __half2* Ch = (__half2*)C;
                Ch[((size_t)row * DIM + col) >> 1]       = __floats2half2_rn(v0, v1);
                Ch[((size_t)(row + 8) * DIM + col) >> 1] = __floats2half2_rn(v2, v3);
            } else {
                float* Cf = (float*)C;
                *(float2*)&Cf[(size_t)row * DIM + col]       = make_float2(v0, v1);
                *(float2*)&Cf[(size_t)(row + 8) * DIM + col] = make_float2(v2, v3);
            }
        }
    }
}

// ---------------------------------------------------------------------------
// Fused RMSNorm+RoPE (y=0: q, y=1: k) AND V-transpose (y=2) in ONE launch.
// Shared buffers overlay in a 16-byte-aligned union.
// ---------------------------------------------------------------------------
struct __align__(16) NTShared {
    union {
        struct {
            float sh[DIM];
            float red[8];
            float s_r;
        } n;
        __half tile[64][80];
    } u;
};

__global__ __launch_bounds__(256) void norm_and_transpose_kernel(
    __half* __restrict__ Xq, __half* __restrict__ Xk,
    const float* __restrict__ gqv, const float* __restrict__ gkv)
{
    __shared__ NTShared S;

    const int t = threadIdx.x;

    if (blockIdx.y == 2) {
        // ---- V transpose: g_vh[s][h*128+d] -> g_vt[h][d][s] ----
        const int bx = blockIdx.x;
        if (bx >= (SEQ / 64) * 2 * NHEADS) return;
        const int sblk = bx % (SEQ / 64);
        const int hz   = bx / (SEQ / 64);       // 0..23
        const int h    = hz >> 1;
        const int d0   = (hz & 1) * 64;
        const int s0   = sblk * 64;

        for (int i = t; i < 512; i += 256) {
            int r = i >> 3, c8 = (i & 7) * 8;
            uint4 v = *(const uint4*)&g_vh[(size_t)(s0 + r) * DIM + h * HDIM + d0 + c8];
            *(uint4*)&S.u.tile[r][c8] = v;
        }
        __syncthreads();
        for (int i = t; i < 512; i += 256) {
            int r = i >> 3, c8 = (i & 7) * 8;
            __half tmp[8];
#pragma unroll
            for (int j = 0; j < 8; ++j) tmp[j] = S.u.tile[c8 + j][r];
            *(uint4*)&g_vt[(size_t)(h * HDIM + d0 + r) * SEQ + s0 + c8] = *(uint4*)tmp;
        }
        return;
    }

    // ---- RMSNorm + RoPE ----
    const int s = blockIdx.x;
    const int which = blockIdx.y;
    __half* X = which ? Xk : Xq;
    const float* g = which ? gkv : gqv;

    __half2* row = (__half2*)(X + (size_t)s * DIM);

    float ss = 0.f;
    for (int i = t; i < DIM / 2; i += 256) {
        float2 f = __half22float2(row[i]);
        S.u.n.sh[2 * i]     = f.x;
        S.u.n.sh[2 * i + 1] = f.y;
        ss += f.x * f.x + f.y * f.y;
    }
#pragma unroll
    for (int off = 16; off > 0; off >>= 1)
        ss += __shfl_xor_sync(0xFFFFFFFFu, ss, off);
    if ((t & 31) == 0) S.u.n.red[t >> 5] = ss;
    __syncthreads();
    if (t == 0) {
        float tot = 0.f;
#pragma unroll
        for (int w = 0; w < 8; w++) tot += S.u.n.red[w];
        S.u.n.s_r = rsqrtf(tot / (float)DIM + EPS);
    }
    __syncthreads();
    const float r = S.u.n.s_r;

    for (int p = t; p < DIM / 2; p += 256) {
        int j = p & 63;
        float c  = g_trig[((size_t)s * 64 + j) * 2 + 0];
        float sn = g_trig[((size_t)s * 64 + j) * 2 + 1];
        float v0 = S.u.n.sh[2 * p] * r * g[2 * p];
        float v1 = S.u.n.sh[2 * p + 1] * r * g[2 * p + 1];
        row[p] = __floats2half2_rn(v0 * c - v1 * sn, v0 * sn + v1 * c);
    }
}

// ---------------------------------------------------------------------------
// fp16 flash attention: cp.async double-buffered K/V + FA2 register P-frags
// + ldmatrix.x4 B-operand loads (R14 measured-best).
// 128 threads (4 warps), BQ=64 (16 rows/warp), BK=64, 2 CTAs/SM.
// ---------------------------------------------------------------------------
#define KSH 136
#define VSH 72
#define FA_SMEM_BYTES ((2 * 64 * KSH + 2 * 128 * VSH) * 2)   // 71680

__global__ __launch_bounds__(128, 2) void flash_h_kernel(
    const __half* __restrict__ Q, const __half* __restrict__ Kg,
    const __half* __restrict__ Vt, __half* __restrict__ O)
{
    extern __shared__ __align__(16) __half smh[];
    __half* Kb[2];
    __half* Vb[2];
    Kb[0] = smh;
    Kb[1] = Kb[0] + 64 * KSH;
    Vb[0] = Kb[1] + 64 * KSH;
    Vb[1] = Vb[0] + 128 * VSH;

    const int h    = blockIdx.y;
    const int qb   = blockIdx.x;
    const int t    = threadIdx.x;
    const int lane = t & 31;
    const int warp = t >> 5;
    const int r0   = lane >> 2;
    const int qc   = lane & 3;
    const float scale = 0.08838834764831845f;   // 1/sqrt(128)

    const int lrow = lane & 7;
    const int ltile = lane >> 3;
    const int offK = lrow * KSH + (ltile >> 1) * 16 + (ltile & 1) * 8;
    const int offV = ((ltile >> 1) * 8 + lrow) * VSH + (ltile & 1) * 8;

    // ---- Stage Q tile into Kb[0], pull A-fragments to registers ----
    {
        const __half* src = Q + (size_t)(qb * 64) * DIM + h * HDIM;
        for (int i = t; i < 64 * 16; i += 128) {
            int r = i >> 4, c8 = (i & 15) * 8;
            *(uint4*)&Kb[0][r * KSH + c8] = *(const uint4*)&src[(size_t)r * DIM + c8];
        }
    }
    __syncthreads();

    unsigned qa[8][4];
    {
        const int rb = warp * 16 + r0;
#pragma unroll
        for (int kt = 0; kt < 8; ++kt) {
            int kc = kt * 16 + 2 * qc;
            qa[kt][0] = ld32h(&Kb[0][rb * KSH + kc]);
            qa[kt][1] = ld32h(&Kb[0][(rb + 8) * KSH + kc]);
            qa[kt][2] = ld32h(&Kb[0][rb * KSH + kc + 8]);
            qa[kt][3] = ld32h(&Kb[0][(rb + 8) * KSH + kc + 8]);
        }
    }
    __syncthreads();

    auto stage_kv = [&](int kb) {
        __half* dk = Kb[kb & 1];
        __half* dv = Vb[kb & 1];
        const __half* ksrc = Kg + (size_t)(kb * 64) * DIM + h * HDIM;
        const __half* vsrc = Vt + (size_t)h * HDIM * SEQ + kb * 64;
        for (int i = t; i < 64 * 16; i += 128) {
            int r = i >> 4, c8 = (i & 15) * 8;
            cp16(&dk[r * KSH + c8], &ksrc[(size_t)r * DIM + c8]);
        }
        for (int i = t; i < 128 * 8; i += 128) {
            int r = i >> 3, c8 = (i & 7) * 8;
            cp16(&dv[r * VSH + c8], &vsrc[(size_t)r * SEQ + c8]);
        }
        cp_commit();
    };

    stage_kv(0);
    stage_kv(1);

    float o[16][4];
#pragma unroll
    for (int nt = 0; nt < 16; ++nt)
#pragma unroll
        for (int j = 0; j < 4; ++j) o[nt][j] = 0.f;

    float m0 = -1e30f, m1 = -1e30f, l0 = 0.f, l1 = 0.f;
    const int NT = SEQ / 64;   // 64

    for (int kb = 0; kb < NT; ++kb) {
        if (kb + 1 < NT) cp_wait<1>(); else cp_wait<0>();
        __syncthreads();

        const __half* Ks = Kb[kb & 1];
        const __half* Vs = Vb[kb & 1];

        // ---- S = Q @ K^T ----
        float s[8][4];
#pragma unroll
        for (int nt = 0; nt < 8; ++nt)
#pragma unroll
            for (int j = 0; j < 4; ++j) s[nt][j] = 0.f;

#pragma unroll
        for (int nt = 0; nt < 8; ++nt) {
            const __half* kbase = Ks + nt * 8 * KSH + offK;
#pragma unroll
            for (int kt2 = 0; kt2 < 4; ++kt2) {
                unsigned b0, b1, b2, b3;
                ldsm_x4(b0, b1, b2, b3, kbase + kt2 * 32);
                mma_f16(s[nt], qa[2 * kt2],     b0, b1);
                mma_f16(s[nt], qa[2 * kt2 + 1], b2, b3);
            }
        }

        // ---- Online softmax ----
        float mx0 = -1e30f, mx1 = -1e30f;
#pragma unroll
        for (int nt = 0; nt < 8; ++nt) {
            mx0 = fmaxf(mx0, fmaxf(s[nt][0], s[nt][1]));
            mx1 = fmaxf(mx1, fmaxf(s[nt][2], s[nt][3]));
        }
        mx0 = fmaxf(mx0, __shfl_xor_sync(0xFFFFFFFFu, mx0, 1));
        mx0 = fmaxf(mx0, __shfl_xor_sync(0xFFFFFFFFu, mx0, 2));
        mx1 = fmaxf(mx1, __shfl_xor_sync(0xFFFFFFFFu, mx1, 1));
        mx1 = fmaxf(mx1, __shfl_xor_sync(0xFFFFFFFFu, mx1, 2));

        float nm0 = fmaxf(m0, mx0 * scale);
        float nm1 = fmaxf(m1, mx1 * scale);
        float corr0 = __expf(m0 - nm0);
        float corr1 = __expf(m1 - nm1);

        float sum0 = 0.f, sum1 = 0.f;
#pragma unroll
        for (int nt = 0; nt < 8; ++nt) {
            s[nt][0] = __expf(s[nt][0] * scale - nm0);
            s[nt][1] = __expf(s[nt][1] * scale - nm0);
            s[nt][2] = __expf(s[nt][2] * scale - nm1);
            s[nt][3] = __expf(s[nt][3] * scale - nm1);
            sum0 += s[nt][0] + s[nt][1];
            sum1 += s[nt][2] + s[nt][3];
        }
        sum0 += __shfl_xor_sync(0xFFFFFFFFu, sum0, 1);
        sum0 += __shfl_xor_sync(0xFFFFFFFFu, sum0, 2);
        sum1 += __shfl_xor_sync(0xFFFFFFFFu, sum1, 1);
        sum1 += __shfl_xor_sync(0xFFFFFFFFu, sum1, 2);

        l0 = l0 * corr0 + sum0;
        l1 = l1 * corr1 + sum1;
        m0 = nm0;
        m1 = nm1;

#pragma unroll
        for (int nt = 0; nt < 16; ++nt) {
            o[nt][0] *= corr0; o[nt][1] *= corr0;
            o[nt][2] *= corr1; o[nt][3] *= corr1;
        }

        // ---- O += P @ V ----
#pragma unroll
        for (int kt = 0; kt < 4; ++kt) {
            unsigned a[4];
            a[0] = packh2(s[2 * kt][0],     s[2 * kt][1]);
            a[1] = packh2(s[2 * kt][2],     s[2 * kt][3]);
            a[2] = packh2(s[2 * kt + 1][0], s[2 * kt + 1][1]);
            a[3] = packh2(s[2 * kt + 1][2], s[2 * kt + 1][3]);
            const __half* vbase = Vs + kt * 16 + offV;
#pragma unroll
            for (int nt2 = 0; nt2 < 8; ++nt2) {
                unsigned b0, b1, b2, b3;
                ldsm_x4(b0, b1, b2, b3, vbase + nt2 * 16 * VSH);
                mma_f16(o[2 * nt2],     a, b0, b1);
                mma_f16(o[2 * nt2 + 1], a, b2, b3);
            }
        }

        __syncthreads();
        if (kb + 2 < NT) stage_kv(kb + 2);
    }

    // ---- Epilogue: normalize, fp16 store ----
    float inv0 = 1.f / l0, inv1 = 1.f / l1;
    int grow = qb * 64 + warp * 16 + r0;
#pragma unroll
    for (int nt = 0; nt < 16; ++nt) {
        int col = h * HDIM + nt * 8 + 2 * qc;
        *(__half2*)&O[(size_t)grow * DIM + col] =
            __floats2half2_rn(o[nt][0] * inv0, o[nt][1] * inv0);
        *(__half2*)&O[(size_t)(grow + 8) * DIM + col] =
            __floats2half2_rn(o[nt][2] * inv1, o[nt][3] * inv1);
    }
}

// ---------------------------------------------------------------------------
// Launch
// ---------------------------------------------------------------------------
extern "C" void kernel_launch(void* const* d_in, const int* in_sizes, int n_in,
                              void* d_out, int out_size)
{
    const float* x     = (const float*)d_in[0];
    const float* freqs = (const float*)d_in[1];
    const float* Wq    = (const float*)d_in[2];
    const float* bq    = (const float*)d_in[3];
    const float* Wk    = (const float*)d_in[4];
    const float* bk    = (const float*)d_in[5];
    const float* Wv    = (const float*)d_in[6];
    const float* bv    = (const float*)d_in[7];
    const float* Wo    = (const float*)d_in[8];
    const float* bo    = (const float*)d_in[9];
    const float* gq    = (const float*)d_in[10];
    const float* gk    = (const float*)d_in[11];
    float* out = (float*)d_out;

    __half *xh, *qh, *kh, *vh, *attnh, *wqh, *wkh, *wvh, *woh, *vt;
    cudaGetSymbolAddress((void**)&xh,    g_xh);
    cudaGetSymbolAddress((void**)&qh,    g_qh);
    cudaGetSymbolAddress((void**)&kh,    g_kh);
    cudaGetSymbolAddress((void**)&vh,    g_vh);
    cudaGetSymbolAddress((void**)&attnh, g_attnh);
    cudaGetSymbolAddress((void**)&wqh,   g_wqh);
    cudaGetSymbolAddress((void**)&wkh,   g_wkh);
    cudaGetSymbolAddress((void**)&wvh,   g_wvh);
    cudaGetSymbolAddress((void**)&woh,   g_woh);
    cudaGetSymbolAddress((void**)&vt,    g_vt);

    cudaFuncSetAttribute(flash_h_kernel,
                         cudaFuncAttributeMaxDynamicSharedMemorySize, FA_SMEM_BYTES);

    // Prep: trig + fp16 conversion (single fused launch).
    trig_kernel<<<(SEQ * 64 + 255) / 256, 256>>>(freqs);
    to_half_all_kernel<<<dim3(SEQ * DIM / 4 / 256, 5), 256>>>(x, Wq, Wk, Wv, Wo);

    // Fused Q/K/V projection (fp16 in/out), ldmatrix operand path.
    dim3 qkv_grid(DIM / 128, SEQ / 128, 3);
    gemm_h_kernel<1><<<qkv_grid, 256>>>(
        xh, wqh, wkh, wvh, bq, bk, bv, qh, kh, vh);

    // RMSNorm+RoPE (q,k) and V transpose in one launch.
    norm_and_transpose_kernel<<<dim3(SEQ, 3), 256>>>(qh, kh, gq, gk);

    // Flash attention: cp.async + register P-frags + ldmatrix.
    flash_h_kernel<<<dim3(SEQ / 64, NHEADS), 128, FA_SMEM_BYTES>>>(qh, kh, vt, attnh);

    // Output projection (fp32 out), ldmatrix operand path.
    dim3 o_grid(DIM / 128, SEQ / 128, 1);
    gemm_h_kernel<0><<<o_grid, 256>>>(
        attnh, woh, woh, woh, bo, bo, bo, out, out, out);
}

// round 16
// speedup vs baseline: 1.9284x; 1.0798x over previous
#include <cuda_runtime.h>
#include <cuda_fp16.h>
#include <math.h>
#include <stdint.h>

// ---------------------------------------------------------------------------
// Problem constants (B=1, S=4096, DIM=1536, HEADS=12, HEAD_DIM=128)
// ---------------------------------------------------------------------------
#define SEQ    4096
#define DIM    1536
#define NHEADS 12
#define HDIM   128
#define EPS    1e-6f

// Scratch (allocation-free rule: __device__ globals)
__device__ __half g_xh[SEQ * DIM];
__device__ __half g_qh[SEQ * DIM];
__device__ __half g_kh[SEQ * DIM];
__device__ __half g_vh[SEQ * DIM];
__device__ __half g_attnh[SEQ * DIM];
__device__ __half g_wqh[DIM * DIM];
__device__ __half g_wkh[DIM * DIM];
__device__ __half g_wvh[DIM * DIM];
__device__ __half g_woh[DIM * DIM];
__device__ __half g_vt[NHEADS * HDIM * SEQ];   // V transposed: [h][d][s]
__device__ float  g_trig[SEQ * 64 * 2];        // cos,sin per (pos, pair)

// ---------------------------------------------------------------------------
// Helpers
// ---------------------------------------------------------------------------
__device__ __forceinline__ unsigned ld32h(const __half* p) {
    return *(const unsigned*)p;
}

__device__ __forceinline__ unsigned packh2(float x, float y) {
    __half2 h = __floats2half2_rn(x, y);
    return *(unsigned*)&h;
}

// D += A*B, m16n8k16, fp16 inputs, f32 accumulate
__device__ __forceinline__ void mma_f16(float* d, const unsigned* a,
                                        unsigned b0, unsigned b1) {
    asm volatile(
        "mma.sync.aligned.m16n8k16.row.col.f32.f16.f16.f32 "
        "{%0,%1,%2,%3}, {%4,%5,%6,%7}, {%8,%9}, {%0,%1,%2,%3};\n"
        : "+f"(d[0]), "+f"(d[1]), "+f"(d[2]), "+f"(d[3])
        : "r"(a[0]), "r"(a[1]), "r"(a[2]), "r"(a[3]), "r"(b0), "r"(b1));
}

// ldmatrix x4: four 8x8 fp16 tiles, one per output register.
__device__ __forceinline__ void ldsm_x4(unsigned& r0, unsigned& r1,
                                        unsigned& r2, unsigned& r3,
                                        const __half* p) {
    unsigned addr = (unsigned)__cvta_generic_to_shared(p);
    asm volatile(
        "ldmatrix.sync.aligned.m8n8.x4.shared.b16 {%0,%1,%2,%3}, [%4];"
        : "=r"(r0), "=r"(r1), "=r"(r2), "=r"(r3) : "r"(addr));
}

__device__ __forceinline__ void cp16(void* smem_dst, const void* gsrc) {
    unsigned s = (unsigned)__cvta_generic_to_shared(smem_dst);
    asm volatile("cp.async.cg.shared.global [%0], [%1], 16;\n" :: "r"(s), "l"(gsrc));
}
__device__ __forceinline__ void cp_commit() {
    asm volatile("cp.async.commit_group;\n");
}
template <int N>
__device__ __forceinline__ void cp_wait() {
    asm volatile("cp.async.wait_group %0;\n" :: "n"(N));
}

// ---------------------------------------------------------------------------
// Prep: fp32 -> fp16, 5 segments in one launch (y: 0=x, 1..4=Wq,Wk,Wv,Wo)
// ---------------------------------------------------------------------------
__global__ __launch_bounds__(256) void to_half_all_kernel(
    const float* __restrict__ x,  const float* __restrict__ Wq,
    const float* __restrict__ Wk, const float* __restrict__ Wv,
    const float* __restrict__ Wo)
{
    const int seg = blockIdx.y;
    const float* src;
    __half* dst;
    int n4;
    if (seg == 0)      { src = x;  dst = g_xh;  n4 = SEQ * DIM / 4; }
    else if (seg == 1) { src = Wq; dst = g_wqh; n4 = DIM * DIM / 4; }
    else if (seg == 2) { src = Wk; dst = g_wkh; n4 = DIM * DIM / 4; }
    else if (seg == 3) { src = Wv; dst = g_wvh; n4 = DIM * DIM / 4; }
    else               { src = Wo; dst = g_woh; n4 = DIM * DIM / 4; }

    int i = blockIdx.x * blockDim.x + threadIdx.x;
    if (i >= n4) return;
    float4 v = ((const float4*)src)[i];
    __half2* d = (__half2*)dst;
    d[2 * i + 0] = __floats2half2_rn(v.x, v.y);
    d[2 * i + 1] = __floats2half2_rn(v.z, v.w);
}

// ---------------------------------------------------------------------------
// RoPE trig table with double-precision range reduction.
// ---------------------------------------------------------------------------
__global__ __launch_bounds__(256) void trig_kernel(const float* __restrict__ freqs) {
    int idx = blockIdx.x * blockDim.x + threadIdx.x;
    if (idx >= SEQ * 64) return;
    double a = (double)freqs[idx];
    double s, c;
    sincos(a, &s, &c);
    g_trig[idx * 2 + 0] = (float)c;
    g_trig[idx * 2 + 1] = (float)s;
}

// ---------------------------------------------------------------------------
// fp16 tensor-core GEMM: ldmatrix.x4 operands + 3-stage cp.async staging.
//   C_z[M,N] = A[M,K] @ W_z[N,K]^T + bias_z[N]  (z = blockIdx.z)
// BM=BN=128, BK=16, 256 threads (8 warps 4m x 2n), warp tile 32x64.
// One __syncthreads per iter; stage(it+2) writes the buffer drained at it-1.
// ---------------------------------------------------------------------------
#define GSH 24

template <int HALF_OUT>
__global__ __launch_bounds__(256, 2) void gemm_h_kernel(
    const __half* __restrict__ A,
    const __half* __restrict__ W0, const __half* __restrict__ W1,
    const __half* __restrict__ W2,
    const float* __restrict__ b0p, const float* __restrict__ b1p,
    const float* __restrict__ b2p,
    void* C0, void* C1, void* C2)
{
    __shared__ __align__(16) __half SB[3][2 * 128 * GSH];   // per stage: A, W

    const int z = blockIdx.z;
    const __half* W   = (z == 0) ? W0  : (z == 1) ? W1  : W2;
    const float* bias = (z == 0) ? b0p : (z == 1) ? b1p : b2p;
    void* C           = (z == 0) ? C0  : (z == 1) ? C1  : C2;

    const int t    = threadIdx.x;
    const int lane = t & 31;
    const int warp = t >> 5;
    const int wm   = warp >> 1;     // 0..3
    const int wn   = warp & 1;      // 0..1
    const int bm   = blockIdx.y * 128;
    const int bn   = blockIdx.x * 128;

    const int lrow = t >> 1;            // 0..127
    const int lc8  = (t & 1) * 8;       // 0 or 8

    const __half* Ap = A + (size_t)(bm + lrow) * DIM + lc8;
    const __half* Wp = W + (size_t)(bn + lrow) * DIM + lc8;

    float c[2][8][4];
#pragma unroll
    for (int mt = 0; mt < 2; mt++)
#pragma unroll
        for (int nt = 0; nt < 8; nt++)
#pragma unroll
            for (int j = 0; j < 4; j++) c[mt][nt][j] = 0.f;

    const int KITERS = DIM / 16;   // 96

    auto stage = [&](int it) {
        __half* as = SB[it % 3];
        __half* ws = as + 128 * GSH;
        cp16(&as[lrow * GSH + lc8], Ap + it * 16);
        cp16(&ws[lrow * GSH + lc8], Wp + it * 16);
        cp_commit();
    };

    stage(0);
    stage(1);

    const int r0  = lane >> 2;
    const int kq  = lane & 3;

    // ldmatrix lane-address components.
    const int tl  = lane & 7;
    const int ti  = lane >> 3;
    const int offA = ((ti & 1) * 8 + tl) * GSH + (ti >> 1) * 8;
    const int offB = ((ti >> 1) * 8 + tl) * GSH + (ti & 1) * 8;

    const int r_a = wm * 32;
    const int r_b = wn * 64;

    for (int it = 0; it < KITERS; ++it) {
        if (it + 1 < KITERS) cp_wait<1>(); else cp_wait<0>();
        __syncthreads();
        if (it + 2 < KITERS) stage(it + 2);

        const __half* as = SB[it % 3];
        const __half* ws = as + 128 * GSH;

        unsigned a[2][4];
#pragma unroll
        for (int mt = 0; mt < 2; ++mt)
            ldsm_x4(a[mt][0], a[mt][1], a[mt][2], a[mt][3],
                    as + (r_a + mt * 16) * GSH + offA);

#pragma unroll
        for (int nt2 = 0; nt2 < 4; ++nt2) {
            unsigned b0, b1, b2, b3;
            ldsm_x4(b0, b1, b2, b3, ws + (r_b + nt2 * 16) * GSH + offB);
            mma_f16(c[0][2 * nt2],     a[0], b0, b1);
            mma_f16(c[1][2 * nt2],     a[1], b0, b1);
            mma_f16(c[0][2 * nt2 + 1], a[0], b2, b3);
            mma_f16(c[1][2 * nt2 + 1], a[1], b2, b3);
        }
    }

    // Epilogue: bias + store
#pragma unroll
    for (int mt = 0; mt < 2; ++mt) {
#pragma unroll
        for (int nt = 0; nt < 8; ++nt) {
            int row = bm + wm * 32 + mt * 16 + r0;
            int col = bn + wn * 64 + nt * 8 + 2 * kq;
            float bb0 = bias[col], bb1 = bias[col + 1];
            float v0 = c[mt][nt][0] + bb0, v1 = c[mt][nt][1] + bb1;
            float v2 = c[mt][nt][2] + bb0, v3 = c[mt][nt][3] + bb1;
            if (HALF_OUT) {
                __half2* Ch = (__half2*)C;
                Ch[((size_t)row * DIM + col) >> 1]       = __floats2half2_rn(v0, v1);
                Ch[((size_t)(row + 8) * DIM + col) >> 1] = __floats2half2_rn(v2, v3);
            } else {
                float* Cf = (float*)C;
                *(float2*)&Cf[(size_t)row * DIM + col]       = make_float2(v0, v1);
                *(float2*)&Cf[(size_t)(row + 8) * DIM + col] = make_float2(v2, v3);
            }
        }
    }
}

// ---------------------------------------------------------------------------
// Fused RMSNorm+RoPE (y=0: q, y=1: k) AND V-transpose (y=2) in ONE launch.
// ---------------------------------------------------------------------------
struct __align__(16) NTShared {
    union {
        struct {
            float sh[DIM];
            float red[8];
            float s_r;
        } n;
        __half tile[64][80];
    } u;
};

__global__ __launch_bounds__(256) void norm_and_transpose_kernel(
    __half* __restrict__ Xq, __half* __restrict__ Xk,
    const float* __restrict__ gqv, const float* __restrict__ gkv)
{
    __shared__ NTShared S;

    const int t = threadIdx.x;

    if (blockIdx.y == 2) {
        const int bx = blockIdx.x;
        if (bx >= (SEQ / 64) * 2 * NHEADS) return;
        const int sblk = bx % (SEQ / 64);
        const int hz   = bx / (SEQ / 64);
        const int h    = hz >> 1;
        const int d0   = (hz & 1) * 64;
        const int s0   = sblk * 64;

        for (int i = t; i < 512; i += 256) {
            int r = i >> 3, c8 = (i & 7) * 8;
            uint4 v = *(const uint4*)&g_vh[(size_t)(s0 + r) * DIM + h * HDIM + d0 + c8];
            *(uint4*)&S.u.tile[r][c8] = v;
        }
        __syncthreads();
        for (int i = t; i < 512; i += 256) {
            int r = i >> 3, c8 = (i & 7) * 8;
            __half tmp[8];
#pragma unroll
            for (int j = 0; j < 8; ++j) tmp[j] = S.u.tile[c8 + j][r];
            *(uint4*)&g_vt[(size_t)(h * HDIM + d0 + r) * SEQ + s0 + c8] = *(uint4*)tmp;
        }
        return;
    }

    const int s = blockIdx.x;
    const int which = blockIdx.y;
    __half* X = which ? Xk : Xq;
    const float* g = which ? gkv : gqv;

    __half2* row = (__half2*)(X + (size_t)s * DIM);

    float ss = 0.f;
    for (int i = t; i < DIM / 2; i += 256) {
        float2 f = __half22float2(row[i]);
        S.u.n.sh[2 * i]     = f.x;
        S.u.n.sh[2 * i + 1] = f.y;
        ss += f.x * f.x + f.y * f.y;
    }
#pragma unroll
    for (int off = 16; off > 0; off >>= 1)
        ss += __shfl_xor_sync(0xFFFFFFFFu, ss, off);
    if ((t & 31) == 0) S.u.n.red[t >> 5] = ss;
    __syncthreads();
    if (t == 0) {
        float tot = 0.f;
#pragma unroll
        for (int w = 0; w < 8; w++) tot += S.u.n.red[w];
        S.u.n.s_r = rsqrtf(tot / (float)DIM + EPS);
    }
    __syncthreads();
    const float r = S.u.n.s_r;

    for (int p = t; p < DIM / 2; p += 256) {
        int j = p & 63;
        float c  = g_trig[((size_t)s * 64 + j) * 2 + 0];
        float sn = g_trig[((size_t)s * 64 + j) * 2 + 1];
        float v0 = S.u.n.sh[2 * p] * r * g[2 * p];
        float v1 = S.u.n.sh[2 * p + 1] * r * g[2 * p + 1];
        row[p] = __floats2half2_rn(v0 * c - v1 * sn, v0 * sn + v1 * c);
    }
}

// ---------------------------------------------------------------------------
// fp16 flash attention (R14/R15 measured-best): cp.async double-buffered K/V
// + FA2 register P-frags + ldmatrix.x4 B-operand loads.
// 128 threads (4 warps), BQ=64 (16 rows/warp), BK=64, 2 CTAs/SM.
// ---------------------------------------------------------------------------
#define KSH 136
#define VSH 72
#define FA_SMEM_BYTES ((2 * 64 * KSH + 2 * 128 * VSH) * 2)   // 71680

__global__ __launch_bounds__(128, 2) void flash_h_kernel(
    const __half* __restrict__ Q, const __half* __restrict__ Kg,
    const __half* __restrict__ Vt, __half* __restrict__ O)
{
    extern __shared__ __align__(16) __half smh[];
    __half* Kb[2];
    __half* Vb[2];
    Kb[0] = smh;
    Kb[1] = Kb[0] + 64 * KSH;
    Vb[0] = Kb[1] + 64 * KSH;
    Vb[1] = Vb[0] + 128 * VSH;

    const int h    = blockIdx.y;
    const int qb   = blockIdx.x;
    const int t    = threadIdx.x;
    const int lane = t & 31;
    const int warp = t >> 5;
    const int r0   = lane >> 2;
    const int qc   = lane & 3;
    const float scale = 0.08838834764831845f;   // 1/sqrt(128)

    const int lrow = lane & 7;
    const int ltile = lane >> 3;
    const int offK = lrow * KSH + (ltile >> 1) * 16 + (ltile & 1) * 8;
    const int offV = ((ltile >> 1) * 8 + lrow) * VSH + (ltile & 1) * 8;

    // ---- Stage Q tile into Kb[0], pull A-fragments to registers ----
    {
        const __half* src = Q + (size_t)(qb * 64) * DIM + h * HDIM;
        for (int i = t; i < 64 * 16; i += 128) {
            int r = i >> 4, c8 = (i & 15) * 8;
            *(uint4*)&Kb[0][r * KSH + c8] = *(const uint4*)&src[(size_t)r * DIM + c8];
        }
    }
    __syncthreads();

    unsigned qa[8][4];
    {
        const int rb = warp * 16 + r0;
#pragma unroll
        for (int kt = 0; kt < 8; ++kt) {
            int kc = kt * 16 + 2 * qc;
            qa[kt][0] = ld32h(&Kb[0][rb * KSH + kc]);
            qa[kt][1] = ld32h(&Kb[0][(rb + 8) * KSH + kc]);
            qa[kt][2] = ld32h(&Kb[0][rb * KSH + kc + 8]);
            qa[kt][3] = ld32h(&Kb[0][(rb + 8) * KSH + kc + 8]);
        }
    }
    __syncthreads();

    auto stage_kv = [&](int kb) {
        __half* dk = Kb[kb & 1];
        __half* dv = Vb[kb & 1];
        const __half* ksrc = Kg + (size_t)(kb * 64) * DIM + h * HDIM;
        const __half* vsrc = Vt + (size_t)h * HDIM * SEQ + kb * 64;
        for (int i = t; i < 64 * 16; i += 128) {
            int r = i >> 4, c8 = (i & 15) * 8;
            cp16(&dk[r * KSH + c8], &ksrc[(size_t)r * DIM + c8]);
        }
        for (int i = t; i < 128 * 8; i += 128) {
            int r = i >> 3, c8 = (i & 7) * 8;
            cp16(&dv[r * VSH + c8], &vsrc[(size_t)r * SEQ + c8]);
        }
        cp_commit();
    };

    stage_kv(0);
    stage_kv(1);

    float o[16][4];
#pragma unroll
    for (int nt = 0; nt < 16; ++nt)
#pragma unroll
        for (int j = 0; j < 4; ++j) o[nt][j] = 0.f;

    float m0 = -1e30f, m1 = -1e30f, l0 = 0.f, l1 = 0.f;
    const int NT = SEQ / 64;   // 64

    for (int kb = 0; kb < NT; ++kb) {
        if (kb + 1 < NT) cp_wait<1>(); else cp_wait<0>();
        __syncthreads();

        const __half* Ks = Kb[kb & 1];
        const __half* Vs = Vb[kb & 1];

        // ---- S = Q @ K^T ----
        float s[8][4];
#pragma unroll
        for (int nt = 0; nt < 8; ++nt)
#pragma unroll
            for (int j = 0; j < 4; ++j) s[nt][j] = 0.f;

#pragma unroll
        for (int nt = 0; nt < 8; ++nt) {
            const __half* kbase = Ks + nt * 8 * KSH + offK;
#pragma unroll
            for (int kt2 = 0; kt2 < 4; ++kt2) {
                unsigned b0, b1, b2, b3;
                ldsm_x4(b0, b1, b2, b3, kbase + kt2 * 32);
                mma_f16(s[nt], qa[2 * kt2],     b0, b1);
                mma_f16(s[nt], qa[2 * kt2 + 1], b2, b3);
            }
        }

        // ---- Online softmax ----
        float mx0 = -1e30f, mx1 = -1e30f;
#pragma unroll
        for (int nt = 0; nt < 8; ++nt) {
            mx0 = fmaxf(mx0, fmaxf(s[nt][0], s[nt][1]));
            mx1 = fmaxf(mx1, fmaxf(s[nt][2], s[nt][3]));
        }
        mx0 = fmaxf(mx0, __shfl_xor_sync(0xFFFFFFFFu, mx0, 1));
        mx0 = fmaxf(mx0, __shfl_xor_sync(0xFFFFFFFFu, mx0, 2));
        mx1 = fmaxf(mx1, __shfl_xor_sync(0xFFFFFFFFu, mx1, 1));
        mx1 = fmaxf(mx1, __shfl_xor_sync(0xFFFFFFFFu, mx1, 2));

        float nm0 = fmaxf(m0, mx0 * scale);
        float nm1 = fmaxf(m1, mx1 * scale);
        float corr0 = __expf(m0 - nm0);
        float corr1 = __expf(m1 - nm1);

        float sum0 = 0.f, sum1 = 0.f;
#pragma unroll
        for (int nt = 0; nt < 8; ++nt) {
            s[nt][0] = __expf(s[nt][0] * scale - nm0);
            s[nt][1] = __expf(s[nt][1] * scale - nm0);
            s[nt][2] = __expf(s[nt][2] * scale - nm1);
            s[nt][3] = __expf(s[nt][3] * scale - nm1);
            sum0 += s[nt][0] + s[nt][1];
            sum1 += s[nt][2] + s[nt][3];
        }
        sum0 += __shfl_xor_sync(0xFFFFFFFFu, sum0, 1);
        sum0 += __shfl_xor_sync(0xFFFFFFFFu, sum0, 2);
        sum1 += __shfl_xor_sync(0xFFFFFFFFu, sum1, 1);
        sum1 += __shfl_xor_sync(0xFFFFFFFFu, sum1, 2);

        l0 = l0 * corr0 + sum0;
        l1 = l1 * corr1 + sum1;
        m0 = nm0;
        m1 = nm1;

#pragma unroll
        for (int nt = 0; nt < 16; ++nt) {
            o[nt][0] *= corr0; o[nt][1] *= corr0;
            o[nt][2] *= corr1; o[nt][3] *= corr1;
        }

        // ---- O += P @ V ----
#pragma unroll
        for (int kt = 0; kt < 4; ++kt) {
            unsigned a[4];
            a[0] = packh2(s[2 * kt][0],     s[2 * kt][1]);
            a[1] = packh2(s[2 * kt][2],     s[2 * kt][3]);
            a[2] = packh2(s[2 * kt + 1][0], s[2 * kt + 1][1]);
            a[3] = packh2(s[2 * kt + 1][2], s[2 * kt + 1][3]);
            const __half* vbase = Vs + kt * 16 + offV;
#pragma unroll
            for (int nt2 = 0; nt2 < 8; ++nt2) {
                unsigned b0, b1, b2, b3;
                ldsm_x4(b0, b1, b2, b3, vbase + nt2 * 16 * VSH);
                mma_f16(o[2 * nt2],     a, b0, b1);
                mma_f16(o[2 * nt2 + 1], a, b2, b3);
            }
        }

        __syncthreads();
        if (kb + 2 < NT) stage_kv(kb + 2);
    }

    // ---- Epilogue: normalize, fp16 store ----
    float inv0 = 1.f / l0, inv1 = 1.f / l1;
    int grow = qb * 64 + warp * 16 + r0;
#pragma unroll
    for (int nt = 0; nt < 16; ++nt) {
        int col = h * HDIM + nt * 8 + 2 * qc;
        *(__half2*)&O[(size_t)grow * DIM + col] =
            __floats2half2_rn(o[nt][0] * inv0, o[nt][1] * inv0);
        *(__half2*)&O[(size_t)(grow + 8) * DIM + col] =
            __floats2half2_rn(o[nt][2] * inv1, o[nt][3] * inv1);
    }
}

// ---------------------------------------------------------------------------
// Launch
// ---------------------------------------------------------------------------
extern "C" void kernel_launch(void* const* d_in, const int* in_sizes, int n_in,
                              void* d_out, int out_size)
{
    const float* x     = (const float*)d_in[0];
    const float* freqs = (const float*)d_in[1];
    const float* Wq    = (const float*)d_in[2];
    const float* bq    = (const float*)d_in[3];
    const float* Wk    = (const float*)d_in[4];
    const float* bk    = (const float*)d_in[5];
    const float* Wv    = (const float*)d_in[6];
    const float* bv    = (const float*)d_in[7];
    const float* Wo    = (const float*)d_in[8];
    const float* bo    = (const float*)d_in[9];
    const float* gq    = (const float*)d_in[10];
    const float* gk    = (const float*)d_in[11];
    float* out = (float*)d_out;

    __half *xh, *qh, *kh, *vh, *attnh, *wqh, *wkh, *wvh, *woh, *vt;
    cudaGetSymbolAddress((void**)&xh,    g_xh);
    cudaGetSymbolAddress((void**)&qh,    g_qh);
    cudaGetSymbolAddress((void**)&kh,    g_kh);
    cudaGetSymbolAddress((void**)&vh,    g_vh);
    cudaGetSymbolAddress((void**)&attnh, g_attnh);
    cudaGetSymbolAddress((void**)&wqh,   g_wqh);
    cudaGetSymbolAddress((void**)&wkh,   g_wkh);
    cudaGetSymbolAddress((void**)&wvh,   g_wvh);
    cudaGetSymbolAddress((void**)&woh,   g_woh);
    cudaGetSymbolAddress((void**)&vt,    g_vt);

    cudaFuncSetAttribute(flash_h_kernel,
                         cudaFuncAttributeMaxDynamicSharedMemorySize, FA_SMEM_BYTES);

    // Prep: trig + fp16 conversion (single fused launch).
    trig_kernel<<<(SEQ * 64 + 255) / 256, 256>>>(freqs);
    to_half_all_kernel<<<dim3(SEQ * DIM / 4 / 256, 5), 256>>>(x, Wq, Wk, Wv, Wo);

    // Fused Q/K/V projection (fp16 in/out), ldmatrix + cp.async pipeline.
    dim3 qkv_grid(DIM / 128, SEQ / 128, 3);
    gemm_h_kernel<1><<<qkv_grid, 256>>>(
        xh, wqh, wkh, wvh, bq, bk, bv, qh, kh, vh);

    // RMSNorm+RoPE (q,k) and V transpose in one launch.
    norm_and_transpose_kernel<<<dim3(SEQ, 3), 256>>>(qh, kh, gq, gk);

    // Flash attention: cp.async + register P-frags + ldmatrix.
    flash_h_kernel<<<dim3(SEQ / 64, NHEADS), 128, FA_SMEM_BYTES>>>(qh, kh, vt, attnh);

    // Output projection (fp32 out), ldmatrix + cp.async pipeline.
    dim3 o_grid(DIM / 128, SEQ / 128, 1);
    gemm_h_kernel<0><<<o_grid, 256>>>(
        attnh, woh, woh, woh, bo, bo, bo, out, out, out);
}

// round 17
// speedup vs baseline: 1.9670x; 1.0200x over previous
#include <cuda_runtime.h>
#include <cuda_fp16.h>
#include <math.h>
#include <stdint.h>

// ---------------------------------------------------------------------------
// Problem constants (B=1, S=4096, DIM=1536, HEADS=12, HEAD_DIM=128)
// ---------------------------------------------------------------------------
#define SEQ    4096
#define DIM    1536
#define NHEADS 12
#define HDIM   128
#define EPS    1e-6f

// Scratch (allocation-free rule: __device__ globals)
__device__ __half g_xh[SEQ * DIM];
__device__ __half g_qh[SEQ * DIM];
__device__ __half g_kh[SEQ * DIM];
__device__ __half g_vh[SEQ * DIM];
__device__ __half g_attnh[SEQ * DIM];
__device__ __half g_wqh[DIM * DIM];
__device__ __half g_wkh[DIM * DIM];
__device__ __half g_wvh[DIM * DIM];
__device__ __half g_woh[DIM * DIM];
__device__ __half g_vt[NHEADS * HDIM * SEQ];   // V transposed: [h][d][s]
__device__ float  g_trig[SEQ * 64 * 2];        // cos,sin per (pos, pair)

// ---------------------------------------------------------------------------
// Helpers
// ---------------------------------------------------------------------------
__device__ __forceinline__ unsigned ld32h(const __half* p) {
    return *(const unsigned*)p;
}

__device__ __forceinline__ unsigned packh2(float x, float y) {
    __half2 h = __floats2half2_rn(x, y);
    return *(unsigned*)&h;
}

__device__ __forceinline__ float ex2(float x) {
    float r;
    asm("ex2.approx.f32 %0, %1;" : "=f"(r) : "f"(x));
    return r;
}

// D += A*B, m16n8k16, fp16 inputs, f32 accumulate
__device__ __forceinline__ void mma_f16(float* d, const unsigned* a,
                                        unsigned b0, unsigned b1) {
    asm volatile(
        "mma.sync.aligned.m16n8k16.row.col.f32.f16.f16.f32 "
        "{%0,%1,%2,%3}, {%4,%5,%6,%7}, {%8,%9}, {%0,%1,%2,%3};\n"
        : "+f"(d[0]), "+f"(d[1]), "+f"(d[2]), "+f"(d[3])
        : "r"(a[0]), "r"(a[1]), "r"(a[2]), "r"(a[3]), "r"(b0), "r"(b1));
}

// ldmatrix x4: four 8x8 fp16 tiles, one per output register.
__device__ __forceinline__ void ldsm_x4(unsigned& r0, unsigned& r1,
                                        unsigned& r2, unsigned& r3,
                                        const __half* p) {
    unsigned addr = (unsigned)__cvta_generic_to_shared(p);
    asm volatile(
        "ldmatrix.sync.aligned.m8n8.x4.shared.b16 {%0,%1,%2,%3}, [%4];"
        : "=r"(r0), "=r"(r1), "=r"(r2), "=r"(r3) : "r"(addr));
}

__device__ __forceinline__ void cp16(void* smem_dst, const void* gsrc) {
    unsigned s = (unsigned)__cvta_generic_to_shared(smem_dst);
    asm volatile("cp.async.cg.shared.global [%0], [%1], 16;\n" :: "r"(s), "l"(gsrc));
}
__device__ __forceinline__ void cp_commit() {
    asm volatile("cp.async.commit_group;\n");
}
template <int N>
__device__ __forceinline__ void cp_wait() {
    asm volatile("cp.async.wait_group %0;\n" :: "n"(N));
}

// ---------------------------------------------------------------------------
// Prep: fp32 -> fp16, 5 segments in one launch (y: 0=x, 1..4=Wq,Wk,Wv,Wo)
// ---------------------------------------------------------------------------
__global__ __launch_bounds__(256) void to_half_all_kernel(
    const float* __restrict__ x,  const float* __restrict__ Wq,
    const float* __restrict__ Wk, const float* __restrict__ Wv,
    const float* __restrict__ Wo)
{
    const int seg = blockIdx.y;
    const float* src;
    __half* dst;
    int n4;
    if (seg == 0)      { src = x;  dst = g_xh;  n4 = SEQ * DIM / 4; }
    else if (seg == 1) { src = Wq; dst = g_wqh; n4 = DIM * DIM / 4; }
    else if (seg == 2) { src = Wk; dst = g_wkh; n4 = DIM * DIM / 4; }
    else if (seg == 3) { src = Wv; dst = g_wvh; n4 = DIM * DIM / 4; }
    else               { src = Wo; dst = g_woh; n4 = DIM * DIM / 4; }

    int i = blockIdx.x * blockDim.x + threadIdx.x;
    if (i >= n4) return;
    float4 v = ((const float4*)src)[i];
    __half2* d = (__half2*)dst;
    d[2 * i + 0] = __floats2half2_rn(v.x, v.y);
    d[2 * i + 1] = __floats2half2_rn(v.z, v.w);
}

// ---------------------------------------------------------------------------
// RoPE trig table with double-precision range reduction.
// ---------------------------------------------------------------------------
__global__ __launch_bounds__(256) void trig_kernel(const float* __restrict__ freqs) {
    int idx = blockIdx.x * blockDim.x + threadIdx.x;
    if (idx >= SEQ * 64) return;
    double a = (double)freqs[idx];
    double s, c;
    sincos(a, &s, &c);
    g_trig[idx * 2 + 0] = (float)c;
    g_trig[idx * 2 + 1] = (float)s;
}

// ---------------------------------------------------------------------------
// fp16 tensor-core GEMM: ldmatrix.x4 operands + 3-stage cp.async, BK=32.
//   C_z[M,N] = A[M,K] @ W_z[N,K]^T + bias_z[N]  (z = blockIdx.z)
// BM=BN=128, 256 threads (8 warps 4m x 2n), warp tile 32x64, 48 k-iters.
// Stride 40 halfs (80B: 5r mod 8 permutation => ldmatrix conflict-free).
// ---------------------------------------------------------------------------
#define GSH 40
#define GEMM_SMEM_BYTES (3 * 2 * 128 * GSH * 2)   // 61440

template <int HALF_OUT>
__global__ __launch_bounds__(256, 2) void gemm_h_kernel(
    const __half* __restrict__ A,
    const __half* __restrict__ W0, const __half* __restrict__ W1,
    const __half* __restrict__ W2,
    const float* __restrict__ b0p, const float* __restrict__ b1p,
    const float* __restrict__ b2p,
    void* C0, void* C1, void* C2)
{
    extern __shared__ __align__(16) __half SBg[];   // [3][2*128*GSH]

    const int z = blockIdx.z;
    const __half* W   = (z == 0) ? W0  : (z == 1) ? W1  : W2;
    const float* bias = (z == 0) ? b0p : (z == 1) ? b1p : b2p;
    void* C           = (z == 0) ? C0  : (z == 1) ? C1  : C2;

    const int t    = threadIdx.x;
    const int lane = t & 31;
    const int warp = t >> 5;
    const int wm   = warp >> 1;     // 0..3
    const int wn   = warp & 1;      // 0..1
    const int bm   = blockIdx.y * 128;
    const int bn   = blockIdx.x * 128;

    const int lrow = t >> 1;            // 0..127
    const int lc   = (t & 1) * 16;      // 0 or 16 (halfs)

    const __half* Ap = A + (size_t)(bm + lrow) * DIM + lc;
    const __half* Wp = W + (size_t)(bn + lrow) * DIM + lc;

    float c[2][8][4];
#pragma unroll
    for (int mt = 0; mt < 2; mt++)
#pragma unroll
        for (int nt = 0; nt < 8; nt++)
#pragma unroll
            for (int j = 0; j < 4; j++) c[mt][nt][j] = 0.f;

    const int KITERS = DIM / 32;   // 48

    auto stage = [&](int it) {
        __half* as = SBg + (it % 3) * (2 * 128 * GSH);
        __half* ws = as + 128 * GSH;
        const __half* ap = Ap + it * 32;
        const __half* wp = Wp + it * 32;
        cp16(&as[lrow * GSH + lc],     ap);
        cp16(&as[lrow * GSH + lc + 8], ap + 8);
        cp16(&ws[lrow * GSH + lc],     wp);
        cp16(&ws[lrow * GSH + lc + 8], wp + 8);
        cp_commit();
    };

    stage(0);
    stage(1);

    const int r0  = lane >> 2;
    const int kq  = lane & 3;

    // ldmatrix lane-address components.
    const int tl  = lane & 7;
    const int ti  = lane >> 3;
    const int offA = ((ti & 1) * 8 + tl) * GSH + (ti >> 1) * 8;
    const int offB = ((ti >> 1) * 8 + tl) * GSH + (ti & 1) * 8;

    const int r_a = wm * 32;
    const int r_b = wn * 64;

    for (int it = 0; it < KITERS; ++it) {
        if (it + 1 < KITERS) cp_wait<1>(); else cp_wait<0>();
        __syncthreads();
        if (it + 2 < KITERS) stage(it + 2);

        const __half* as = SBg + (it % 3) * (2 * 128 * GSH);
        const __half* ws = as + 128 * GSH;

#pragma unroll
        for (int kt = 0; kt < 2; ++kt) {
            const int ko = kt * 16;
            unsigned a[2][4];
#pragma unroll
            for (int mt = 0; mt < 2; ++mt)
                ldsm_x4(a[mt][0], a[mt][1], a[mt][2], a[mt][3],
                        as + (r_a + mt * 16) * GSH + offA + ko);

#pragma unroll
            for (int nt2 = 0; nt2 < 4; ++nt2) {
                unsigned b0, b1, b2, b3;
                ldsm_x4(b0, b1, b2, b3, ws + (r_b + nt2 * 16) * GSH + offB + ko);
                mma_f16(c[0][2 * nt2],     a[0], b0, b1);
                mma_f16(c[1][2 * nt2],     a[1], b0, b1);
                mma_f16(c[0][2 * nt2 + 1], a[0], b2, b3);
                mma_f16(c[1][2 * nt2 + 1], a[1], b2, b3);
            }
        }
    }

    // Epilogue: bias + store
#pragma unroll
    for (int mt = 0; mt < 2; ++mt) {
#pragma unroll
        for (int nt = 0; nt < 8; ++nt) {
            int row = bm + wm * 32 + mt * 16 + r0;
            int col = bn + wn * 64 + nt * 8 + 2 * kq;
            float bb0 = bias[col], bb1 = bias[col + 1];
            float v0 = c[mt][nt][0] + bb0, v1 = c[mt][nt][1] + bb1;
            float v2 = c[mt][nt][2] + bb0, v3 = c[mt][nt][3] + bb1;
            if (HALF_OUT) {
                __half2* Ch = (__half2*)C;
                Ch[((size_t)row * DIM + col) >> 1]       = __floats2half2_rn(v0, v1);
                Ch[((size_t)(row + 8) * DIM + col) >> 1] = __floats2half2_rn(v2, v3);
            } else {
                float* Cf = (float*)C;
                *(float2*)&Cf[(size_t)row * DIM + col]       = make_float2(v0, v1);
                *(float2*)&Cf[(size_t)(row + 8) * DIM + col] = make_float2(v2, v3);
            }
        }
    }
}

// ---------------------------------------------------------------------------
// Fused RMSNorm+RoPE (y=0: q, y=1: k) AND V-transpose (y=2) in ONE launch.
// ---------------------------------------------------------------------------
struct __align__(16) NTShared {
    union {
        struct {
            float sh[DIM];
            float red[8];
            float s_r;
        } n;
        __half tile[64][80];
    } u;
};

__global__ __launch_bounds__(256) void norm_and_transpose_kernel(
    __half* __restrict__ Xq, __half* __restrict__ Xk,
    const float* __restrict__ gqv, const float* __restrict__ gkv)
{
    __shared__ NTShared S;

    const int t = threadIdx.x;

    if (blockIdx.y == 2) {
        const int bx = blockIdx.x;
        if (bx >= (SEQ / 64) * 2 * NHEADS) return;
        const int sblk = bx % (SEQ / 64);
        const int hz   = bx / (SEQ / 64);
        const int h    = hz >> 1;
        const int d0   = (hz & 1) * 64;
        const int s0   = sblk * 64;

        for (int i = t; i < 512; i += 256) {
            int r = i >> 3, c8 = (i & 7) * 8;
            uint4 v = *(const uint4*)&g_vh[(size_t)(s0 + r) * DIM + h * HDIM + d0 + c8];
            *(uint4*)&S.u.tile[r][c8] = v;
        }
        __syncthreads();
        for (int i = t; i < 512; i += 256) {
            int r = i >> 3, c8 = (i & 7) * 8;
            __half tmp[8];
#pragma unroll
            for (int j = 0; j < 8; ++j) tmp[j] = S.u.tile[c8 + j][r];
            *(uint4*)&g_vt[(size_t)(h * HDIM + d0 + r) * SEQ + s0 + c8] = *(uint4*)tmp;
        }
        return;
    }

    const int s = blockIdx.x;
    const int which = blockIdx.y;
    __half* X = which ? Xk : Xq;
    const float* g = which ? gkv : gqv;

    __half2* row = (__half2*)(X + (size_t)s * DIM);

    float ss = 0.f;
    for (int i = t; i < DIM / 2; i += 256) {
        float2 f = __half22float2(row[i]);
        S.u.n.sh[2 * i]     = f.x;
        S.u.n.sh[2 * i + 1] = f.y;
        ss += f.x * f.x + f.y * f.y;
    }
#pragma unroll
    for (int off = 16; off > 0; off >>= 1)
        ss += __shfl_xor_sync(0xFFFFFFFFu, ss, off);
    if ((t & 31) == 0) S.u.n.red[t >> 5] = ss;
    __syncthreads();
    if (t == 0) {
        float tot = 0.f;
#pragma unroll
        for (int w = 0; w < 8; w++) tot += S.u.n.red[w];
        S.u.n.s_r = rsqrtf(tot / (float)DIM + EPS);
    }
    __syncthreads();
    const float r = S.u.n.s_r;

    for (int p = t; p < DIM / 2; p += 256) {
        int j = p & 63;
        float c  = g_trig[((size_t)s * 64 + j) * 2 + 0];
        float sn = g_trig[((size_t)s * 64 + j) * 2 + 1];
        float v0 = S.u.n.sh[2 * p] * r * g[2 * p];
        float v1 = S.u.n.sh[2 * p + 1] * r * g[2 * p + 1];
        row[p] = __floats2half2_rn(v0 * c - v1 * sn, v0 * sn + v1 * c);
    }
}

// ---------------------------------------------------------------------------
// fp16 flash attention: 3-stage cp.async K/V ring + FA2 register P-frags
// + ldmatrix.x4 B-operands + exp2-domain softmax.
// 128 threads (4 warps), BQ=64 (16 rows/warp), BK=64, 2 CTAs/SM.
// ---------------------------------------------------------------------------
#define KSH 136
#define VSH 72
#define FA_STAGE_H (64 * KSH + 128 * VSH)                 // halfs per stage
#define FA_SMEM_BYTES (3 * FA_STAGE_H * 2)                // 107520

__global__ __launch_bounds__(128, 2) void flash_h_kernel(
    const __half* __restrict__ Q, const __half* __restrict__ Kg,
    const __half* __restrict__ Vt, __half* __restrict__ O)
{
    extern __shared__ __align__(16) __half smh[];
    // stage layout: [K tile 64*KSH][V tile 128*VSH] x3

    const int h    = blockIdx.y;
    const int qb   = blockIdx.x;
    const int t    = threadIdx.x;
    const int lane = t & 31;
    const int warp = t >> 5;
    const int r0   = lane >> 2;
    const int qc   = lane & 3;
    const float c2 = 0.12753076f;   // (1/sqrt(128)) * log2(e)

    const int lrow = lane & 7;
    const int ltile = lane >> 3;
    const int offK = lrow * KSH + (ltile >> 1) * 16 + (ltile & 1) * 8;
    const int offV = ((ltile >> 1) * 8 + lrow) * VSH + (ltile & 1) * 8;

    // ---- Stage Q tile into stage-0 buffer, pull A-fragments to registers ----
    {
        const __half* src = Q + (size_t)(qb * 64) * DIM + h * HDIM;
        for (int i = t; i < 64 * 16; i += 128) {
            int r = i >> 4, c8 = (i & 15) * 8;
            *(uint4*)&smh[r * KSH + c8] = *(const uint4*)&src[(size_t)r * DIM + c8];
        }
    }
    __syncthreads();

    unsigned qa[8][4];
    {
        const int rb = warp * 16 + r0;
#pragma unroll
        for (int kt = 0; kt < 8; ++kt) {
            int kc = kt * 16 + 2 * qc;
            qa[kt][0] = ld32h(&smh[rb * KSH + kc]);
            qa[kt][1] = ld32h(&smh[(rb + 8) * KSH + kc]);
            qa[kt][2] = ld32h(&smh[rb * KSH + kc + 8]);
            qa[kt][3] = ld32h(&smh[(rb + 8) * KSH + kc + 8]);
        }
    }
    __syncthreads();

    auto stage_kv = [&](int kb) {
        __half* dk = smh + (kb % 3) * FA_STAGE_H;
        __half* dv = dk + 64 * KSH;
        const __half* ksrc = Kg + (size_t)(kb * 64) * DIM + h * HDIM;
        const __half* vsrc = Vt + (size_t)h * HDIM * SEQ + kb * 64;
        for (int i = t; i < 64 * 16; i += 128) {
            int r = i >> 4, c8 = (i & 15) * 8;
            cp16(&dk[r * KSH + c8], &ksrc[(size_t)r * DIM + c8]);
        }
        for (int i = t; i < 128 * 8; i += 128) {
            int r = i >> 3, c8 = (i & 7) * 8;
            cp16(&dv[r * VSH + c8], &vsrc[(size_t)r * SEQ + c8]);
        }
        cp_commit();
    };

    stage_kv(0);
    stage_kv(1);
    stage_kv(2);

    float o[16][4];
#pragma unroll
    for (int nt = 0; nt < 16; ++nt)
#pragma unroll
        for (int j = 0; j < 4; ++j) o[nt][j] = 0.f;

    // Running max in log2 domain.
    float m0 = -1e30f, m1 = -1e30f, l0 = 0.f, l1 = 0.f;
    const int NT = SEQ / 64;   // 64

    for (int kb = 0; kb < NT; ++kb) {
        if (kb + 2 < NT)      cp_wait<2>();
        else if (kb + 1 < NT) cp_wait<1>();
        else                  cp_wait<0>();
        __syncthreads();

        const __half* Ks = smh + (kb % 3) * FA_STAGE_H;
        const __half* Vs = Ks + 64 * KSH;

        // ---- S = Q @ K^T ----
        float s[8][4];
#pragma unroll
        for (int nt = 0; nt < 8; ++nt)
#pragma unroll
            for (int j = 0; j < 4; ++j) s[nt][j] = 0.f;

#pragma unroll
        for (int nt = 0; nt < 8; ++nt) {
            const __half* kbase = Ks + nt * 8 * KSH + offK;
#pragma unroll
            for (int kt2 = 0; kt2 < 4; ++kt2) {
                unsigned b0, b1, b2, b3;
                ldsm_x4(b0, b1, b2, b3, kbase + kt2 * 32);
                mma_f16(s[nt], qa[2 * kt2],     b0, b1);
                mma_f16(s[nt], qa[2 * kt2 + 1], b2, b3);
            }
        }

        // ---- Online softmax in exp2 domain ----
        float mx0 = -1e30f, mx1 = -1e30f;
#pragma unroll
        for (int nt = 0; nt < 8; ++nt) {
            mx0 = fmaxf(mx0, fmaxf(s[nt][0], s[nt][1]));
            mx1 = fmaxf(mx1, fmaxf(s[nt][2], s[nt][3]));
        }
        mx0 = fmaxf(mx0, __shfl_xor_sync(0xFFFFFFFFu, mx0, 1));
        mx0 = fmaxf(mx0, __shfl_xor_sync(0xFFFFFFFFu, mx0, 2));
        mx1 = fmaxf(mx1, __shfl_xor_sync(0xFFFFFFFFu, mx1, 1));
        mx1 = fmaxf(mx1, __shfl_xor_sync(0xFFFFFFFFu, mx1, 2));

        float nm0 = fmaxf(m0, mx0 * c2);
        float nm1 = fmaxf(m1, mx1 * c2);
        float corr0 = ex2(m0 - nm0);
        float corr1 = ex2(m1 - nm1);

        float sum0 = 0.f, sum1 = 0.f;
#pragma unroll
        for (int nt = 0; nt < 8; ++nt) {
            s[nt][0] = ex2(fmaf(s[nt][0], c2, -nm0));
            s[nt][1] = ex2(fmaf(s[nt][1], c2, -nm0));
            s[nt][2] = ex2(fmaf(s[nt][2], c2, -nm1));
            s[nt][3] = ex2(fmaf(s[nt][3], c2, -nm1));
            sum0 += s[nt][0] + s[nt][1];
            sum1 += s[nt][2] + s[nt][3];
        }
        sum0 += __shfl_xor_sync(0xFFFFFFFFu, sum0, 1);
        sum0 += __shfl_xor_sync(0xFFFFFFFFu, sum0, 2);
        sum1 += __shfl_xor_sync(0xFFFFFFFFu, sum1, 1);
        sum1 += __shfl_xor_sync(0xFFFFFFFFu, sum1, 2);

        l0 = l0 * corr0 + sum0;
        l1 = l1 * corr1 + sum1;
        m0 = nm0;
        m1 = nm1;

#pragma unroll
        for (int nt = 0; nt < 16; ++nt) {
            o[nt][0] *= corr0; o[nt][1] *= corr0;
            o[nt][2] *= corr1; o[nt][3] *= corr1;
        }

        // ---- O += P @ V ----
#pragma unroll
        for (int kt = 0; kt < 4; ++kt) {
            unsigned a[4];
            a[0] = packh2(s[2 * kt][0],     s[2 * kt][1]);
            a[1] = packh2(s[2 * kt][2],     s[2 * kt][3]);
            a[2] = packh2(s[2 * kt + 1][0], s[2 * kt + 1][1]);
            a[3] = packh2(s[2 * kt + 1][2], s[2 * kt + 1][3]);
            const __half* vbase = Vs + kt * 16 + offV;
#pragma unroll
            for (int nt2 = 0; nt2 < 8; ++nt2) {
                unsigned b0, b1, b2, b3;
                ldsm_x4(b0, b1, b2, b3, vbase + nt2 * 16 * VSH);
                mma_f16(o[2 * nt2],     a, b0, b1);
                mma_f16(o[2 * nt2 + 1], a, b2, b3);
            }
        }

        __syncthreads();                 // buffer kb%3 fully consumed
        if (kb + 3 < NT) stage_kv(kb + 3);
    }

    // ---- Epilogue: normalize, fp16 store ----
    float inv0 = 1.f / l0, inv1 = 1.f / l1;
    int grow = qb * 64 + warp * 16 + r0;
#pragma unroll
    for (int nt = 0; nt < 16; ++nt) {
        int col = h * HDIM + nt * 8 + 2 * qc;
        *(__half2*)&O[(size_t)grow * DIM + col] =
            __floats2half2_rn(o[nt][0] * inv0, o[nt][1] * inv0);
        *(__half2*)&O[(size_t)(grow + 8) * DIM + col] =
            __floats2half2_rn(o[nt][2] * inv1, o[nt][3] * inv1);
    }
}

// ---------------------------------------------------------------------------
// Launch
// ---------------------------------------------------------------------------
extern "C" void kernel_launch(void* const* d_in, const int* in_sizes, int n_in,
                              void* d_out, int out_size)
{
    const float* x     = (const float*)d_in[0];
    const float* freqs = (const float*)d_in[1];
    const float* Wq    = (const float*)d_in[2];
    const float* bq    = (const float*)d_in[3];
    const float* Wk    = (const float*)d_in[4];
    const float* bk    = (const float*)d_in[5];
    const float* Wv    = (const float*)d_in[6];
    const float* bv    = (const float*)d_in[7];
    const float* Wo    = (const float*)d_in[8];
    const float* bo    = (const float*)d_in[9];
    const float* gq    = (const float*)d_in[10];
    const float* gk    = (const float*)d_in[11];
    float* out = (float*)d_out;

    __half *xh, *qh, *kh, *vh, *attnh, *wqh, *wkh, *wvh, *woh, *vt;
    cudaGetSymbolAddress((void**)&xh,    g_xh);
    cudaGetSymbolAddress((void**)&qh,    g_qh);
    cudaGetSymbolAddress((void**)&kh,    g_kh);
    cudaGetSymbolAddress((void**)&vh,    g_vh);
    cudaGetSymbolAddress((void**)&attnh, g_attnh);
    cudaGetSymbolAddress((void**)&wqh,   g_wqh);
    cudaGetSymbolAddress((void**)&wkh,   g_wkh);
    cudaGetSymbolAddress((void**)&wvh,   g_wvh);
    cudaGetSymbolAddress((void**)&woh,   g_woh);
    cudaGetSymbolAddress((void**)&vt,    g_vt);

    cudaFuncSetAttribute(flash_h_kernel,
                         cudaFuncAttributeMaxDynamicSharedMemorySize, FA_SMEM_BYTES);
    cudaFuncSetAttribute(gemm_h_kernel<1>,
                         cudaFuncAttributeMaxDynamicSharedMemorySize, GEMM_SMEM_BYTES);
    cudaFuncSetAttribute(gemm_h_kernel<0>,
                         cudaFuncAttributeMaxDynamicSharedMemorySize, GEMM_SMEM_BYTES);

    // Prep: trig + fp16 conversion (single fused launch).
    trig_kernel<<<(SEQ * 64 + 255) / 256, 256>>>(freqs);
    to_half_all_kernel<<<dim3(SEQ * DIM / 4 / 256, 5), 256>>>(x, Wq, Wk, Wv, Wo);

    // Fused Q/K/V projection (fp16 in/out), ldmatrix + cp.async, BK=32.
    dim3 qkv_grid(DIM / 128, SEQ / 128, 3);
    gemm_h_kernel<1><<<qkv_grid, 256, GEMM_SMEM_BYTES>>>(
        xh, wqh, wkh, wvh, bq, bk, bv, qh, kh, vh);

    // RMSNorm+RoPE (q,k) and V transpose in one launch.
    norm_and_transpose_kernel<<<dim3(SEQ, 3), 256>>>(qh, kh, gq, gk);

    // Flash attention: 3-stage cp.async + register P-frags + ldmatrix + exp2.
    flash_h_kernel<<<dim3(SEQ / 64, NHEADS), 128, FA_SMEM_BYTES>>>(qh, kh, vt, attnh);

    // Output projection (fp32 out).
    dim3 o_grid(DIM / 128, SEQ / 128, 1);
    gemm_h_kernel<0><<<o_grid, 256, GEMM_SMEM_BYTES>>>(
        attnh, woh, woh, woh, bo, bo, bo, out, out, out);
}